// round 2
// baseline (speedup 1.0000x reference)
#include <cuda_runtime.h>
#include <cstdint>

// Problem constants
#define BB   8192
#define FF   64
#define VV   1000
#define EE   64
#define TT   2
#define NTOKN 16
#define GG   4
#define DD   256
#define KK   128          // T*E
#define SBK  4            // samples per block
#define MT   64           // M tile = SBK*NTOKN

#define WT_PAD 260        // Wt row pitch (floats), 16B-aligned, conflict-free
#define XT_PAD 68         // xT row pitch
#define H_PAD  264        // hbuf row pitch

// smem byte offsets
#define OFF_WT   0
#define OFF_XT   133120   // 128*260*4
#define OFF_MS   167936   // +128*68*4
#define OFF_IDS  200704   // +2*64*64*4
#define OFF_MK   201728
#define OFF_GX   202752
#define OFF_B    203008
#define OFF_G    204032
#define OFF_BT   205056
#define SMEM_BYTES 206080

__device__ int g_is64;

// Detect whether int_feats is int64 (values < 1000, so high 32-bit words are all 0)
// or int32 (odd words are independent random ids; P(128 zeros) ~ 0).
__global__ void detect_kernel(const unsigned int* __restrict__ p) {
    if (threadIdx.x == 0) {
        int all0 = 1;
        #pragma unroll 1
        for (int i = 1; i < 256; i += 2) all0 &= (p[i] == 0u);
        g_is64 = all0;
    }
}

__device__ __forceinline__ unsigned long long pack2(float a, float b) {
    unsigned long long r;
    asm("mov.b64 %0, {%1, %2};" : "=l"(r) : "f"(a), "f"(b));
    return r;
}
__device__ __forceinline__ void unpack2(unsigned long long v, float& a, float& b) {
    asm("mov.b64 {%0, %1}, %2;" : "=f"(a), "=f"(b) : "l"(v));
}
// Blackwell packed fp32 FMA: 2 MACs per instruction, exact fp32 numerics.
__device__ __forceinline__ void ffma2(unsigned long long& d, unsigned long long a,
                                      unsigned long long b) {
    asm("fma.rn.f32x2 %0, %1, %2, %0;" : "+l"(d) : "l"(a), "l"(b));
}

__global__ __launch_bounds__(256, 1)
void fused_tokenizer_kernel(const void*  __restrict__ ids_raw,
                            const int*   __restrict__ mask,
                            const int*   __restrict__ gidx,
                            const float* __restrict__ tbl,
                            const float* __restrict__ missing,
                            const float* __restrict__ W,
                            const float* __restrict__ bias,
                            const float* __restrict__ gamma,
                            const float* __restrict__ beta,
                            float*       __restrict__ out)
{
    extern __shared__ char smem[];
    float* Wt   = (float*)(smem + OFF_WT);   // [KK][WT_PAD]   W transposed
    float* xT   = (float*)(smem + OFF_XT);   // [KK][XT_PAD]   x transposed (k-major)
    float* msS  = (float*)(smem + OFF_MS);   // [TT*FF*EE]     missing emb
    int*   idsS = (int*)  (smem + OFF_IDS);  // [SBK*FF]
    float* mkS  = (float*)(smem + OFF_MK);   // [SBK*FF]
    int*   gxS  = (int*)  (smem + OFF_GX);   // [NTOKN*GG]
    float* bS   = (float*)(smem + OFF_B);
    float* gS   = (float*)(smem + OFF_G);
    float* btS  = (float*)(smem + OFF_BT);

    const int tid = threadIdx.x;
    const int s0  = blockIdx.x * SBK;   // first sample of this block
    const int is64 = g_is64;

    // ---- Stage W (transposed) into smem ----
    for (int i = tid; i < DD * KK; i += 256) {
        int n = i >> 7, k = i & 127;
        Wt[k * WT_PAD + n] = W[i];
    }
    // ---- Stage missing embeddings (flat copy) ----
    for (int i = tid; i < TT * FF * EE; i += 256) msS[i] = missing[i];
    // ---- ids + masks for the 4 samples (SBK*FF == 256 == blockDim) ----
    {
        int gi = s0 * FF + tid;
        int idv = is64 ? (int)((const long long*)ids_raw)[gi]
                       : ((const int*)ids_raw)[gi];
        idsS[tid] = idv;
        mkS[tid]  = (float)mask[gi];
    }
    if (tid < NTOKN * GG) gxS[tid] = gidx[tid];
    if (tid < DD) { bS[tid] = bias[tid]; gS[tid] = gamma[tid]; btS[tid] = beta[tid]; }
    __syncthreads();

    // ---- Gather + group-mean pool: build xT[k][m], m = sample*16 + token ----
    // elem = m*128 + k so that a warp covers 32 consecutive e's -> coalesced 128B gathers.
    #pragma unroll 4
    for (int it = 0; it < (MT * KK) / 256; ++it) {
        int elem = tid + 256 * it;
        int m = elem >> 7, k = elem & 127;
        int s = m >> 4, n = m & 15;
        int tf_base = (k >> 6) * FF;     // t*64
        int e = k & 63;
        float sum = 0.f;
        #pragma unroll
        for (int g = 0; g < GG; ++g) {
            int f   = gxS[n * GG + g];
            int tf  = tf_base + f;
            int idv = idsS[s * FF + f];
            float v = tbl[((size_t)(tf * VV + idv) << 6) + e];
            v += mkS[s * FF + f] * msS[(tf << 6) + e];
            sum += v;
        }
        xT[k * XT_PAD + m] = 0.25f * sum;
    }
    __syncthreads();

    // ---- GEMM: 64 x 256 x 128, register tile 4m x 16n per thread (f32x2) ----
    const int ti = tid >> 4;   // 0..15 -> m block (4 rows)
    const int tj = tid & 15;   // 0..15 -> n chunks: n = q*64 + tj*4 + {0..3}
    unsigned long long acc[4][8];
    #pragma unroll
    for (int a = 0; a < 4; ++a)
        #pragma unroll
        for (int c = 0; c < 8; ++c) acc[a][c] = 0ull;

    const float* xTb = xT + ti * 4;
    const float* Wtb = Wt + tj * 4;

    #pragma unroll 4
    for (int k = 0; k < KK; ++k) {
        float4 xv = *(const float4*)(xTb + k * XT_PAD);
        unsigned long long xx0 = pack2(xv.x, xv.x);
        unsigned long long xx1 = pack2(xv.y, xv.y);
        unsigned long long xx2 = pack2(xv.z, xv.z);
        unsigned long long xx3 = pack2(xv.w, xv.w);
        #pragma unroll
        for (int q = 0; q < 4; ++q) {
            ulonglong2 wv = *(const ulonglong2*)(Wtb + k * WT_PAD + q * 64);
            ffma2(acc[0][q*2],   xx0, wv.x); ffma2(acc[0][q*2+1], xx0, wv.y);
            ffma2(acc[1][q*2],   xx1, wv.x); ffma2(acc[1][q*2+1], xx1, wv.y);
            ffma2(acc[2][q*2],   xx2, wv.x); ffma2(acc[2][q*2+1], xx2, wv.y);
            ffma2(acc[3][q*2],   xx3, wv.x); ffma2(acc[3][q*2+1], xx3, wv.y);
        }
    }
    __syncthreads();   // done reading Wt -> safe to reuse as hbuf

    // ---- bias + SiLU, stage h into smem ----
    float* hbuf = (float*)smem;   // [MT][H_PAD], reuses Wt region
    #pragma unroll
    for (int mi = 0; mi < 4; ++mi) {
        int m = ti * 4 + mi;
        #pragma unroll
        for (int q = 0; q < 4; ++q) {
            int n0 = q * 64 + tj * 4;
            float v0, v1, v2, v3;
            unpack2(acc[mi][q*2],   v0, v1);
            unpack2(acc[mi][q*2+1], v2, v3);
            v0 += bS[n0];     v1 += bS[n0+1];
            v2 += bS[n0+2];   v3 += bS[n0+3];
            v0 = v0 / (1.f + __expf(-v0));
            v1 = v1 / (1.f + __expf(-v1));
            v2 = v2 / (1.f + __expf(-v2));
            v3 = v3 / (1.f + __expf(-v3));
            float4 h4 = make_float4(v0, v1, v2, v3);
            *(float4*)(hbuf + m * H_PAD + n0) = h4;
        }
    }
    __syncthreads();

    // ---- LayerNorm per row (warp w handles rows w*8 .. w*8+7) ----
    const int lane = tid & 31;
    const int wrp  = tid >> 5;
    #pragma unroll 1
    for (int r = 0; r < 8; ++r) {
        int m = wrp * 8 + r;
        float v[8];
        float sum = 0.f, sq = 0.f;
        #pragma unroll
        for (int j = 0; j < 8; ++j) {
            v[j] = hbuf[m * H_PAD + lane + 32 * j];
            sum += v[j];
            sq  += v[j] * v[j];
        }
        #pragma unroll
        for (int o = 16; o; o >>= 1) {
            sum += __shfl_xor_sync(0xffffffffu, sum, o);
            sq  += __shfl_xor_sync(0xffffffffu, sq,  o);
        }
        float mu  = sum * (1.f / 256.f);
        float var = sq * (1.f / 256.f) - mu * mu;
        float inv = rsqrtf(var + 1e-5f);
        size_t ob = ((size_t)(s0 * NTOKN) + m) * DD;
        #pragma unroll
        for (int j = 0; j < 8; ++j) {
            int d = lane + 32 * j;
            out[ob + d] = (v[j] - mu) * inv * gS[d] + btS[d];
        }
    }
}

extern "C" void kernel_launch(void* const* d_in, const int* in_sizes, int n_in,
                              void* d_out, int out_size) {
    const void*  ids     = d_in[0];                 // int_feats (int32 or int64)
    const int*   mask    = (const int*)  d_in[1];   // missing_mask int32
    const int*   gidx    = (const int*)  d_in[2];   // group_idx int32 [16][4]
    const float* tbl     = (const float*)d_in[3];   // emb_tables [2][64][1000][64]
    const float* missing = (const float*)d_in[4];   // missing_emb [2][64][64]
    const float* W       = (const float*)d_in[5];   // [256][128]
    const float* b       = (const float*)d_in[6];   // [256]
    const float* gamma   = (const float*)d_in[7];   // [256]
    const float* beta    = (const float*)d_in[8];   // [256]
    float* out = (float*)d_out;                     // [8192][16][256]

    cudaFuncSetAttribute(fused_tokenizer_kernel,
                         cudaFuncAttributeMaxDynamicSharedMemorySize, SMEM_BYTES);

    detect_kernel<<<1, 32>>>((const unsigned int*)ids);
    fused_tokenizer_kernel<<<BB / SBK, 256, SMEM_BYTES>>>(
        ids, mask, gidx, tbl, missing, W, b, gamma, beta, out);
}

// round 3
// speedup vs baseline: 1.1156x; 1.1156x over previous
#include <cuda_runtime.h>
#include <cstdint>

// Problem constants
#define BB    8192
#define FF    64
#define VV    1000
#define EE    64
#define TT    2
#define NTOKN 16
#define GG    4
#define DD    256
#define KK    128          // T*E
#define SBK   8            // samples per group
#define MT    128          // M tile = SBK*NTOKN
#define NGRP  (BB / SBK)   // 1024 groups
#define NTHR  512

#define WT_PAD 260         // Wt row pitch (floats)
#define XT_PAD 132         // xT row pitch (floats)

// smem layout (bytes)
#define OFF_WT   0
#define OFF_XT   (128 * WT_PAD * 4)              // 133120
#define OFF_IDS  (OFF_XT + 128 * XT_PAD * 4)     // +67584 = 200704
#define OFF_MK   (OFF_IDS + 512 * 4)             // 202752
#define OFF_GX   (OFF_MK + 512 * 4)              // 204800
#define OFF_B    (OFF_GX + 256)                  // 205056
#define OFF_G    (OFF_B + 1024)
#define OFF_BT   (OFF_G + 1024)
#define SMEM_BYTES (OFF_BT + 1024)               // 208128

__device__ int g_is64;

// Detect int32 vs int64 int_feats: values < 1000 so int64 high words are 0.
__global__ void detect_kernel(const unsigned int* __restrict__ p) {
    if (threadIdx.x == 0) {
        int all0 = 1;
        #pragma unroll 1
        for (int i = 1; i < 256; i += 2) all0 &= (p[i] == 0u);
        g_is64 = all0;
    }
}

__device__ __forceinline__ unsigned long long pack2(float a, float b) {
    unsigned long long r;
    asm("mov.b64 %0, {%1, %2};" : "=l"(r) : "f"(a), "f"(b));
    return r;
}
__device__ __forceinline__ void unpack2(unsigned long long v, float& a, float& b) {
    asm("mov.b64 {%0, %1}, %2;" : "=f"(a), "=f"(b) : "l"(v));
}
// Blackwell packed fp32 FMA: 2 exact fp32 MACs per instruction.
__device__ __forceinline__ void ffma2(unsigned long long& d, unsigned long long a,
                                      unsigned long long b) {
    asm("fma.rn.f32x2 %0, %1, %2, %0;" : "+l"(d) : "l"(a), "l"(b));
}

__global__ __launch_bounds__(NTHR, 1)
void fused_tokenizer_kernel(const void*  __restrict__ ids_raw,
                            const int*   __restrict__ mask,
                            const int*   __restrict__ gidx,
                            const float* __restrict__ tbl,
                            const float* __restrict__ missing,
                            const float* __restrict__ W,
                            const float* __restrict__ bias,
                            const float* __restrict__ gamma,
                            const float* __restrict__ beta,
                            float*       __restrict__ out,
                            int nblocks)
{
    extern __shared__ char smem[];
    float* Wt   = (float*)(smem + OFF_WT);   // [KK][WT_PAD]  W transposed
    float* xT   = (float*)(smem + OFF_XT);   // [KK][XT_PAD]  x transposed (k-major)
    int*   idsS = (int*)  (smem + OFF_IDS);  // [SBK*FF]
    float* mkS  = (float*)(smem + OFF_MK);   // [SBK*FF]
    int*   gxS  = (int*)  (smem + OFF_GX);   // [NTOKN*GG]
    float* bS   = (float*)(smem + OFF_B);
    float* gS   = (float*)(smem + OFF_G);
    float* btS  = (float*)(smem + OFF_BT);

    const int tid  = threadIdx.x;
    const int is64 = g_is64;

    // ---- One-time staging: W (transposed), group idx, bias/gamma/beta ----
    for (int i = tid; i < DD * KK; i += NTHR) {
        int n = i >> 7, k = i & 127;
        Wt[k * WT_PAD + n] = W[i];
    }
    if (tid < NTOKN * GG) gxS[tid] = gidx[tid];
    if (tid < DD) { bS[tid] = bias[tid]; gS[tid] = gamma[tid]; btS[tid] = beta[tid]; }

    // Per-thread constants for gather: k fixed across iterations
    const int kg  = tid & 127;        // k index this thread gathers
    const int e   = kg & 63;
    const int tt  = kg >> 6;
    const int mb  = tid >> 7;         // m base (0..3)
    float* xrow = xT + (size_t)kg * XT_PAD;

    // GEMM thread mapping
    const int ti = tid >> 4;          // 0..31 -> m block of 4
    const int tj = tid & 15;          // 0..15 -> n = q*64 + tj*4 + {0..3}
    const float* xTb = xT + ti * 4;
    const float* Wtb = Wt + tj * 4;
    const float4 b4[4] = { *(const float4*)(bS + 0*64 + tj*4),
                           *(const float4*)(bS + 1*64 + tj*4),
                           *(const float4*)(bS + 2*64 + tj*4),
                           *(const float4*)(bS + 3*64 + tj*4) };

    for (int grp = blockIdx.x; grp < NGRP; grp += nblocks) {
        __syncthreads();   // previous group's GEMM reads done; safe to overwrite

        // ---- ids + masks for 8 samples (512 values == 512 threads) ----
        {
            int gi = grp * (SBK * FF) + tid;
            idsS[tid] = is64 ? (int)((const long long*)ids_raw)[gi]
                             : ((const int*)ids_raw)[gi];
            mkS[tid]  = (float)mask[gi];
        }
        __syncthreads();

        // ---- Gather + group-mean pool -> xT[k][m] ----
        // Warp-uniform (m,s,n); lanes cover 32 consecutive e -> 128B coalesced.
        #pragma unroll 4
        for (int it = 0; it < MT / 4; ++it) {
            int m = mb + (it << 2);
            int n = m & 15, s = m >> 4;
            const int* gx = gxS + n * GG;
            float sum = 0.f;
            #pragma unroll
            for (int g = 0; g < GG; ++g) {
                int f   = gx[g];
                int tf  = tt * FF + f;
                int idv = idsS[s * FF + f];
                sum += __ldg(tbl + (((size_t)(tf * VV + idv)) << 6) + e);
                if (mkS[s * FF + f] != 0.f)            // warp-uniform branch
                    sum += __ldg(missing + ((size_t)tf << 6) + e);
            }
            xrow[m] = 0.25f * sum;
        }
        __syncthreads();

        // ---- GEMM 128 x 256 x 128, per-thread 4m x 16n (f32x2 accumulators) ----
        unsigned long long acc[4][8];
        #pragma unroll
        for (int a = 0; a < 4; ++a)
            #pragma unroll
            for (int c = 0; c < 8; ++c) acc[a][c] = 0ull;

        #pragma unroll 4
        for (int k = 0; k < KK; ++k) {
            float4 xv = *(const float4*)(xTb + k * XT_PAD);
            unsigned long long xx0 = pack2(xv.x, xv.x);
            unsigned long long xx1 = pack2(xv.y, xv.y);
            unsigned long long xx2 = pack2(xv.z, xv.z);
            unsigned long long xx3 = pack2(xv.w, xv.w);
            #pragma unroll
            for (int q = 0; q < 4; ++q) {
                ulonglong2 wv = *(const ulonglong2*)(Wtb + k * WT_PAD + q * 64);
                ffma2(acc[0][q*2],   xx0, wv.x); ffma2(acc[0][q*2+1], xx0, wv.y);
                ffma2(acc[1][q*2],   xx1, wv.x); ffma2(acc[1][q*2+1], xx1, wv.y);
                ffma2(acc[2][q*2],   xx2, wv.x); ffma2(acc[2][q*2+1], xx2, wv.y);
                ffma2(acc[3][q*2],   xx3, wv.x); ffma2(acc[3][q*2+1], xx3, wv.y);
            }
        }

        // ---- Epilogue: bias + SiLU in regs, LayerNorm via half-warp shuffles ----
        // Row m's 256 values live on the 16 threads sharing ti (a half-warp).
        #pragma unroll
        for (int mi = 0; mi < 4; ++mi) {
            int m = ti * 4 + mi;
            float h[16];
            float sum = 0.f, sq = 0.f;
            #pragma unroll
            for (int q = 0; q < 4; ++q) {
                float v0, v1, v2, v3;
                unpack2(acc[mi][q*2],   v0, v1);
                unpack2(acc[mi][q*2+1], v2, v3);
                v0 += b4[q].x; v1 += b4[q].y; v2 += b4[q].z; v3 += b4[q].w;
                v0 = v0 / (1.f + __expf(-v0));
                v1 = v1 / (1.f + __expf(-v1));
                v2 = v2 / (1.f + __expf(-v2));
                v3 = v3 / (1.f + __expf(-v3));
                h[q*4+0] = v0; h[q*4+1] = v1; h[q*4+2] = v2; h[q*4+3] = v3;
                sum += v0 + v1 + v2 + v3;
                sq  += v0*v0 + v1*v1 + v2*v2 + v3*v3;
            }
            #pragma unroll
            for (int o = 8; o; o >>= 1) {     // 16-lane (half-warp) reduce
                sum += __shfl_xor_sync(0xffffffffu, sum, o);
                sq  += __shfl_xor_sync(0xffffffffu, sq,  o);
            }
            float mu  = sum * (1.f / 256.f);
            float var = sq * (1.f / 256.f) - mu * mu;
            float inv = rsqrtf(var + 1e-5f);
            size_t ob = ((size_t)grp * MT + m) * DD;
            #pragma unroll
            for (int q = 0; q < 4; ++q) {
                int n0 = q * 64 + tj * 4;
                float4 o4;
                o4.x = (h[q*4+0] - mu) * inv * gS[n0+0] + btS[n0+0];
                o4.y = (h[q*4+1] - mu) * inv * gS[n0+1] + btS[n0+1];
                o4.z = (h[q*4+2] - mu) * inv * gS[n0+2] + btS[n0+2];
                o4.w = (h[q*4+3] - mu) * inv * gS[n0+3] + btS[n0+3];
                *(float4*)(out + ob + n0) = o4;
            }
        }
    }
}

extern "C" void kernel_launch(void* const* d_in, const int* in_sizes, int n_in,
                              void* d_out, int out_size) {
    const void*  ids     = d_in[0];                 // int_feats (int32 or int64)
    const int*   mask    = (const int*)  d_in[1];
    const int*   gidx    = (const int*)  d_in[2];
    const float* tbl     = (const float*)d_in[3];
    const float* missing = (const float*)d_in[4];
    const float* W       = (const float*)d_in[5];
    const float* b       = (const float*)d_in[6];
    const float* gamma   = (const float*)d_in[7];
    const float* beta    = (const float*)d_in[8];
    float* out = (float*)d_out;

    int nsm = 0;
    cudaDeviceGetAttribute(&nsm, cudaDevAttrMultiProcessorCount, 0);
    if (nsm <= 0) nsm = 148;

    cudaFuncSetAttribute(fused_tokenizer_kernel,
                         cudaFuncAttributeMaxDynamicSharedMemorySize, SMEM_BYTES);

    detect_kernel<<<1, 32>>>((const unsigned int*)ids);
    fused_tokenizer_kernel<<<nsm, NTHR, SMEM_BYTES>>>(
        ids, mask, gidx, tbl, missing, W, b, gamma, beta, out, nsm);
}

// round 6
// speedup vs baseline: 2.0985x; 1.8811x over previous
#include <cuda_runtime.h>
#include <cuda_bf16.h>
#include <cstdint>

#define BB    8192
#define FF    64
#define VV    1000
#define NTOKN 16
#define GG    4
#define DD    256
#define KK    128
#define SBK   8
#define MT    128          // rows per group = SBK*NTOKN
#define NGRP  (BB / SBK)
#define NTHR  512

#define PADB  272          // bytes per bf16 tile row (136 bf16): conflict-free ldmatrix
#define HPITCH 264         // hstage pitch in floats

// smem byte offsets
#define OFF_BHI  0                         // W hi bf16 [256][136]   69632 B
#define OFF_BLO  69632                     // W lo                   69632 B
#define OFF_AHI  139264                    // x hi bf16 [128][136]   34816 B
#define OFF_ALO  174080                    // x lo                   34816 B
// hstage (64 rows x 264 floats = 67584 B) reuses [OFF_AHI, OFF_AHI+67584)
#define OFF_IDS  208896                    // 512 ints
#define OFF_MK   210944                    // 512 floats
#define OFF_GX   212992                    // 64 ints
#define OFF_BIA  213248                    // 256 floats
#define OFF_GAM  214272
#define OFF_BET  215296
#define OFF_PSUM 216320                    // [128][2] floats
#define OFF_PSQ  217344
#define OFF_MUI  218368                    // 128 float2
#define SMEM_BYTES 219392

__device__ int g_is64;

__global__ void detect_kernel(const unsigned int* __restrict__ p) {
    if (threadIdx.x == 0) {
        int all0 = 1;
        #pragma unroll 1
        for (int i = 1; i < 256; i += 2) all0 &= (p[i] == 0u);
        g_is64 = all0;
    }
}

__device__ __forceinline__ uint32_t smem_u32(const void* p) {
    uint32_t a;
    asm("{ .reg .u64 t; cvta.to.shared.u64 t, %1; cvt.u32.u64 %0, t; }" : "=r"(a) : "l"(p));
    return a;
}
__device__ __forceinline__ void ldm4(uint32_t* r, uint32_t addr) {
    asm volatile("ldmatrix.sync.aligned.m8n8.x4.shared.b16 {%0,%1,%2,%3}, [%4];"
                 : "=r"(r[0]), "=r"(r[1]), "=r"(r[2]), "=r"(r[3]) : "r"(addr));
}
__device__ __forceinline__ void mma16816(float* c, const uint32_t* a,
                                         uint32_t b0, uint32_t b1) {
    asm volatile("mma.sync.aligned.m16n8k16.row.col.f32.bf16.bf16.f32 "
                 "{%0,%1,%2,%3}, {%4,%5,%6,%7}, {%8,%9}, {%0,%1,%2,%3};"
                 : "+f"(c[0]), "+f"(c[1]), "+f"(c[2]), "+f"(c[3])
                 : "r"(a[0]), "r"(a[1]), "r"(a[2]), "r"(a[3]), "r"(b0), "r"(b1));
}
__device__ __forceinline__ float silu(float v) { return v / (1.f + __expf(-v)); }

__global__ __launch_bounds__(NTHR, 1)
void fused_tokenizer_kernel(const void*  __restrict__ ids_raw,
                            const int*   __restrict__ mask,
                            const int*   __restrict__ gidx,
                            const float* __restrict__ tbl,
                            const float* __restrict__ missing,
                            const float* __restrict__ W,
                            const float* __restrict__ bias,
                            const float* __restrict__ gamma,
                            const float* __restrict__ beta,
                            float*       __restrict__ out,
                            int nblocks)
{
    extern __shared__ char smem[];
    const uint32_t sb = smem_u32(smem);
    int*    idsS = (int*)   (smem + OFF_IDS);
    float*  mkS  = (float*) (smem + OFF_MK);
    int*    gxS  = (int*)   (smem + OFF_GX);
    float*  bS   = (float*) (smem + OFF_BIA);
    float*  gS   = (float*) (smem + OFF_GAM);
    float*  btS  = (float*) (smem + OFF_BET);
    float*  psum = (float*) (smem + OFF_PSUM);
    float*  psq  = (float*) (smem + OFF_PSQ);
    float2* mui  = (float2*)(smem + OFF_MUI);
    float*  hstage = (float*)(smem + OFF_AHI);   // reuses A region post-GEMM

    const int tid  = threadIdx.x;
    const int wid  = tid >> 5;
    const int lane = tid & 31;
    const int is64 = g_is64;

    // ---- One-time: split W into bf16 hi/lo padded tiles ----
    for (int i = tid; i < DD * KK; i += NTHR) {
        int n = i >> 7, k = i & 127;
        float w = W[i];
        __nv_bfloat16 hi = __float2bfloat16(w);
        __nv_bfloat16 lo = __float2bfloat16(w - __bfloat162float(hi));
        uint32_t off = (uint32_t)n * PADB + ((uint32_t)k << 1);
        *(__nv_bfloat16*)(smem + OFF_BHI + off) = hi;
        *(__nv_bfloat16*)(smem + OFF_BLO + off) = lo;
    }
    if (tid < NTOKN * GG) gxS[tid] = gidx[tid];
    if (tid < DD) { bS[tid] = bias[tid]; gS[tid] = gamma[tid]; btS[tid] = beta[tid]; }

    // gather constants: thread owns k = kg, iterates rows m
    const int kg = tid & 127;
    const int e  = kg & 63;
    const int tt = kg >> 6;
    const int mb = tid >> 7;
    const uint32_t aoff = (uint32_t)kg << 1;

    // GEMM warp mapping: mw = m-tile (16 rows), nh = n-half (128 cols)
    const int mw = wid & 7;
    const int nh = wid >> 3;
    const uint32_t paH = sb + OFF_AHI + (uint32_t)(mw * 16 + (lane & 15)) * PADB
                       + (uint32_t)(lane >> 4) * 16;
    const uint32_t paL = paH + (OFF_ALO - OFF_AHI);
    const int g8 = lane >> 3;
    const uint32_t pb = sb + ((g8 < 2) ? OFF_BHI : OFF_BLO)
                      + (uint32_t)(nh * 128 + (lane & 7)) * PADB
                      + (uint32_t)(g8 & 1) * 16;

    // epilogue rows
    const int r0 = mw * 16 + (lane >> 2);
    const int r1 = r0 + 8;
    const int ncol = nh * 128 + (lane & 3) * 2;

    for (int grp = blockIdx.x; grp < NGRP; grp += nblocks) {
        __syncthreads();
        {   // ids + masks (512 values == 512 threads)
            int gi = grp * (SBK * FF) + tid;
            idsS[tid] = is64 ? (int)((const long long*)ids_raw)[gi]
                             : ((const int*)ids_raw)[gi];
            mkS[tid]  = (float)mask[gi];
        }
        __syncthreads();

        // ---- gather + pool -> split-bf16 A tiles ----
        #pragma unroll 4
        for (int it = 0; it < MT / 4; ++it) {
            int m = mb + (it << 2);
            int n = m & 15, s = m >> 4;
            const int* gx = gxS + n * GG;
            float sum = 0.f;
            #pragma unroll
            for (int g = 0; g < GG; ++g) {
                int f   = gx[g];
                int tf  = tt * FF + f;
                int idv = idsS[s * FF + f];
                sum += __ldg(tbl + (((size_t)(tf * VV + idv)) << 6) + e);
                if (mkS[s * FF + f] != 0.f)                 // warp-uniform
                    sum += __ldg(missing + ((size_t)tf << 6) + e);
            }
            float x = 0.25f * sum;
            __nv_bfloat16 hi = __float2bfloat16(x);
            __nv_bfloat16 lo = __float2bfloat16(x - __bfloat162float(hi));
            uint32_t off = (uint32_t)m * PADB + aoff;
            *(__nv_bfloat16*)(smem + OFF_AHI + off) = hi;
            *(__nv_bfloat16*)(smem + OFF_ALO + off) = lo;
        }
        __syncthreads();

        // ---- GEMM: D = Ahi*Bhi^T + Ahi*Blo^T + Alo*Bhi^T (HMMA) ----
        float acc[16][4];
        #pragma unroll
        for (int j = 0; j < 16; ++j)
            #pragma unroll
            for (int c = 0; c < 4; ++c) acc[j][c] = 0.f;

        #pragma unroll 1
        for (int s = 0; s < 8; ++s) {
            uint32_t aH[4], aL[4];
            ldm4(aH, paH + s * 32);
            ldm4(aL, paL + s * 32);
            #pragma unroll
            for (int j = 0; j < 16; ++j) {
                uint32_t b[4];
                ldm4(b, pb + (uint32_t)j * (8 * PADB) + s * 32);
                mma16816(acc[j], aH, b[0], b[1]);   // hi*hi
                mma16816(acc[j], aH, b[2], b[3]);   // hi*lo
                mma16816(acc[j], aL, b[0], b[1]);   // lo*hi
            }
        }

        // ---- epilogue A: bias + SiLU in regs, quad-reduce row sums ----
        float s0 = 0.f, q0 = 0.f, s1 = 0.f, q1 = 0.f;
        #pragma unroll
        for (int j = 0; j < 16; ++j) {
            int c = ncol + j * 8;
            float2 bb = *(float2*)(bS + c);
            float v0 = silu(acc[j][0] + bb.x);
            float v1 = silu(acc[j][1] + bb.y);
            float v2 = silu(acc[j][2] + bb.x);
            float v3 = silu(acc[j][3] + bb.y);
            acc[j][0] = v0; acc[j][1] = v1; acc[j][2] = v2; acc[j][3] = v3;
            s0 += v0 + v1; q0 += v0 * v0 + v1 * v1;
            s1 += v2 + v3; q1 += v2 * v2 + v3 * v3;
        }
        #pragma unroll
        for (int o = 1; o <= 2; o <<= 1) {   // reduce over the 4-lane quad
            s0 += __shfl_xor_sync(0xffffffffu, s0, o);
            q0 += __shfl_xor_sync(0xffffffffu, q0, o);
            s1 += __shfl_xor_sync(0xffffffffu, s1, o);
            q1 += __shfl_xor_sync(0xffffffffu, q1, o);
        }
        if ((lane & 3) == 0) {
            psum[r0 * 2 + nh] = s0;  psq[r0 * 2 + nh] = q0;
            psum[r1 * 2 + nh] = s1;  psq[r1 * 2 + nh] = q1;
        }
        __syncthreads();

        if (tid < MT) {
            float sm = psum[tid * 2] + psum[tid * 2 + 1];
            float qq = psq [tid * 2] + psq [tid * 2 + 1];
            float mu  = sm * (1.f / 256.f);
            float var = qq * (1.f / 256.f) - mu * mu;
            mui[tid] = make_float2(mu, rsqrtf(var + 1e-5f));
        }
        __syncthreads();

        // ---- epilogue B: normalize -> hstage (reuses A) -> coalesced store ----
        #pragma unroll 1
        for (int p = 0; p < 2; ++p) {
            if ((mw >> 2) == p) {
                float2 u0 = mui[r0], u1 = mui[r1];
                int lr0 = r0 - p * 64, lr1 = r1 - p * 64;
                #pragma unroll
                for (int j = 0; j < 16; ++j) {
                    int c = ncol + j * 8;
                    float2 gg = *(float2*)(gS  + c);
                    float2 be = *(float2*)(btS + c);
                    float2 o0, o1;
                    o0.x = (acc[j][0] - u0.x) * u0.y * gg.x + be.x;
                    o0.y = (acc[j][1] - u0.x) * u0.y * gg.y + be.y;
                    o1.x = (acc[j][2] - u1.x) * u1.y * gg.x + be.x;
                    o1.y = (acc[j][3] - u1.x) * u1.y * gg.y + be.y;
                    *(float2*)(hstage + lr0 * HPITCH + c) = o0;
                    *(float2*)(hstage + lr1 * HPITCH + c) = o1;
                }
            }
            __syncthreads();
            {   // coalesced copy: 64 rows x 256 cols
                int row = tid >> 3, cb = (tid & 7) * 4;
                const float* src = hstage + row * HPITCH;
                float* dst = out + ((size_t)grp * MT + p * 64 + row) * DD;
                #pragma unroll
                for (int i2 = 0; i2 < 8; ++i2) {
                    int c = cb + i2 * 32;
                    *(float4*)(dst + c) = *(const float4*)(src + c);
                }
            }
            __syncthreads();
        }
    }
}

extern "C" void kernel_launch(void* const* d_in, const int* in_sizes, int n_in,
                              void* d_out, int out_size) {
    const void*  ids     = d_in[0];
    const int*   mask    = (const int*)  d_in[1];
    const int*   gidx    = (const int*)  d_in[2];
    const float* tbl     = (const float*)d_in[3];
    const float* missing = (const float*)d_in[4];
    const float* W       = (const float*)d_in[5];
    const float* b       = (const float*)d_in[6];
    const float* gamma   = (const float*)d_in[7];
    const float* beta    = (const float*)d_in[8];
    float* out = (float*)d_out;

    int nsm = 0;
    cudaDeviceGetAttribute(&nsm, cudaDevAttrMultiProcessorCount, 0);
    if (nsm <= 0) nsm = 148;
    if (nsm > NGRP) nsm = NGRP;

    cudaFuncSetAttribute(fused_tokenizer_kernel,
                         cudaFuncAttributeMaxDynamicSharedMemorySize, SMEM_BYTES);

    detect_kernel<<<1, 32>>>((const unsigned int*)ids);
    fused_tokenizer_kernel<<<nsm, NTHR, SMEM_BYTES>>>(
        ids, mask, gidx, tbl, missing, W, b, gamma, beta, out, nsm);
}

// round 7
// speedup vs baseline: 2.8373x; 1.3521x over previous
#include <cuda_runtime.h>
#include <cuda_bf16.h>
#include <cstdint>

#define BB    8192
#define FF    64
#define VV    1000
#define NTOKN 16
#define GG    4
#define DD    256
#define KK    128
#define SBK   8
#define MT    128          // rows per group = SBK*NTOKN
#define NGRP  (BB / SBK)
#define NTHR  512

#define PADB  272          // bytes per bf16 tile row (136 bf16): conflict-free ldmatrix

// smem byte offsets
#define OFF_BHI  0                         // W hi bf16 [256][136]   69632 B
#define OFF_BLO  69632                     // W lo                   69632 B
#define OFF_AHI  139264                    // x hi bf16 [128][136]   34816 B
#define OFF_ALO  174080                    // x lo                   34816 B
#define OFF_QS   208896                    // 512 ints: packed (offset<<1)|mask
#define OFF_GX   210944                    // 64 ints
#define OFF_BIA  211200                    // 256 floats
#define OFF_GAM  212224
#define OFF_BET  213248
#define OFF_PSUM 214272                    // [128][4] floats
#define OFF_PSQ  216320                    // [128][4] floats
#define SMEM_BYTES 218368

__device__ int g_is64;

__global__ void detect_kernel(const unsigned int* __restrict__ p) {
    if (threadIdx.x == 0) {
        int all0 = 1;
        #pragma unroll 1
        for (int i = 1; i < 256; i += 2) all0 &= (p[i] == 0u);
        g_is64 = all0;
    }
}

__device__ __forceinline__ uint32_t smem_u32(const void* p) {
    uint32_t a;
    asm("{ .reg .u64 t; cvta.to.shared.u64 t, %1; cvt.u32.u64 %0, t; }" : "=r"(a) : "l"(p));
    return a;
}
__device__ __forceinline__ void ldm4(uint32_t* r, uint32_t addr) {
    asm volatile("ldmatrix.sync.aligned.m8n8.x4.shared.b16 {%0,%1,%2,%3}, [%4];"
                 : "=r"(r[0]), "=r"(r[1]), "=r"(r[2]), "=r"(r[3]) : "r"(addr));
}
__device__ __forceinline__ void mma16816(float* c, const uint32_t* a,
                                         uint32_t b0, uint32_t b1) {
    asm volatile("mma.sync.aligned.m16n8k16.row.col.f32.bf16.bf16.f32 "
                 "{%0,%1,%2,%3}, {%4,%5,%6,%7}, {%8,%9}, {%0,%1,%2,%3};"
                 : "+f"(c[0]), "+f"(c[1]), "+f"(c[2]), "+f"(c[3])
                 : "r"(a[0]), "r"(a[1]), "r"(a[2]), "r"(a[3]), "r"(b0), "r"(b1));
}
__device__ __forceinline__ float silu(float v) { return v / (1.f + __expf(-v)); }

__global__ __launch_bounds__(NTHR, 1)
void fused_tokenizer_kernel(const void*  __restrict__ ids_raw,
                            const int*   __restrict__ mask,
                            const int*   __restrict__ gidx,
                            const float* __restrict__ tbl,
                            const float* __restrict__ missing,
                            const float* __restrict__ W,
                            const float* __restrict__ bias,
                            const float* __restrict__ gamma,
                            const float* __restrict__ beta,
                            float*       __restrict__ out,
                            int nblocks)
{
    extern __shared__ char smem[];
    const uint32_t sb = smem_u32(smem);
    int*    qS   = (int*)   (smem + OFF_QS);
    int*    gxS  = (int*)   (smem + OFF_GX);
    float*  bS   = (float*) (smem + OFF_BIA);
    float*  gS   = (float*) (smem + OFF_GAM);
    float*  btS  = (float*) (smem + OFF_BET);
    float*  psum = (float*) (smem + OFF_PSUM);
    float*  psq  = (float*) (smem + OFF_PSQ);

    const int tid  = threadIdx.x;
    const int wid  = tid >> 5;
    const int lane = tid & 31;
    const int is64 = g_is64;

    // ---- One-time: split W into bf16 hi/lo padded tiles ----
    for (int i = tid; i < DD * KK; i += NTHR) {
        int n = i >> 7, k = i & 127;
        float w = W[i];
        __nv_bfloat16 hi = __float2bfloat16(w);
        __nv_bfloat16 lo = __float2bfloat16(w - __bfloat162float(hi));
        uint32_t off = (uint32_t)n * PADB + ((uint32_t)k << 1);
        *(__nv_bfloat16*)(smem + OFF_BHI + off) = hi;
        *(__nv_bfloat16*)(smem + OFF_BLO + off) = lo;
    }
    if (tid < NTOKN * GG) gxS[tid] = gidx[tid];
    if (tid < DD) { bS[tid] = bias[tid]; gS[tid] = gamma[tid]; btS[tid] = beta[tid]; }
    __syncthreads();

    // ---- gather constants: warp owns (tt, mb); lane owns e-pair ----
    const int tt = wid & 1;               // table
    const int mb = wid >> 1;              // m ≡ mb (mod 8)
    const float* gbase = tbl + (size_t)tt * 4096000 + (lane << 1);   // + q
    const float* mbase = missing + tt * 4096 + (lane << 1);          // + f*64
    int f0[GG], f1[GG];
    #pragma unroll
    for (int g = 0; g < GG; ++g) {
        f0[g] = gxS[mb * GG + g];         // token n = mb
        f1[g] = gxS[(mb + 8) * GG + g];   // token n = mb+8
    }
    const uint32_t abase = sb + OFF_AHI + (uint32_t)(((tt << 6) + (lane << 1)) << 1);

    // ---- GEMM warp mapping: 32m x 64n tiles (4m x 4n warp grid) ----
    const int mq = wid & 3;
    const int nq = wid >> 2;
    const uint32_t paH = sb + OFF_AHI + (uint32_t)(mq * 32 + (lane & 15)) * PADB
                       + (uint32_t)(lane >> 4) * 16;
    const uint32_t paL = paH + (OFF_ALO - OFF_AHI);
    const int g8 = lane >> 3;
    const uint32_t pb = sb + ((g8 < 2) ? OFF_BHI : OFF_BLO)
                      + (uint32_t)(nq * 64 + (lane & 7)) * PADB
                      + (uint32_t)(g8 & 1) * 16;
    const int cbase = nq * 64 + (lane & 3) * 2;

    for (int grp = blockIdx.x; grp < NGRP; grp += nblocks) {
        __syncthreads();
        {   // stage packed (gather-offset<<1)|mask per (s,f); 512 == NTHR
            int gi  = grp * (SBK * FF) + tid;
            int idv = is64 ? (int)((const long long*)ids_raw)[gi]
                           : ((const int*)ids_raw)[gi];
            int f   = tid & 63;
            qS[tid] = (((f * VV + idv) << 6) << 1) | mask[gi];
        }
        __syncthreads();

        // ---- gather + pool (float2 per thread) -> split-bf16 A tiles ----
        #pragma unroll 4
        for (int it = 0; it < 16; ++it) {
            int m = mb + (it << 3);
            int s = it >> 1;
            const int* fs = (it & 1) ? f1 : f0;
            float sx = 0.f, sy = 0.f;
            #pragma unroll
            for (int g = 0; g < GG; ++g) {
                int f  = fs[g];
                int qm = qS[(s << 6) + f];
                float2 v = __ldg((const float2*)(gbase + (qm >> 1)));
                sx += v.x; sy += v.y;
                if (qm & 1) {                       // warp-uniform
                    float2 w2 = __ldg((const float2*)(mbase + (f << 6)));
                    sx += w2.x; sy += w2.y;
                }
            }
            sx *= 0.25f; sy *= 0.25f;
            __nv_bfloat16 h0 = __float2bfloat16(sx);
            __nv_bfloat16 h1 = __float2bfloat16(sy);
            __nv_bfloat162 hp = __halves2bfloat162(h0, h1);
            __nv_bfloat162 lp = __floats2bfloat162_rn(sx - __bfloat162float(h0),
                                                      sy - __bfloat162float(h1));
            uint32_t off = (uint32_t)m * PADB;
            *(uint32_t*)((char*)smem + (abase - sb) + off) = *(uint32_t*)&hp;
            *(uint32_t*)((char*)smem + (abase - sb) + (OFF_ALO - OFF_AHI) + off) = *(uint32_t*)&lp;
        }
        __syncthreads();

        // ---- GEMM: D = Ahi*Bhi^T + Ahi*Blo^T + Alo*Bhi^T (HMMA) ----
        float acc[2][8][4];
        #pragma unroll
        for (int t = 0; t < 2; ++t)
            #pragma unroll
            for (int j = 0; j < 8; ++j)
                #pragma unroll
                for (int c = 0; c < 4; ++c) acc[t][j][c] = 0.f;

        #pragma unroll 1
        for (int s = 0; s < 8; ++s) {
            uint32_t aH0[4], aH1[4], aL0[4], aL1[4];
            ldm4(aH0, paH + s * 32);
            ldm4(aH1, paH + 16 * PADB + s * 32);
            ldm4(aL0, paL + s * 32);
            ldm4(aL1, paL + 16 * PADB + s * 32);
            #pragma unroll
            for (int j = 0; j < 8; ++j) {
                uint32_t b[4];
                ldm4(b, pb + (uint32_t)j * (8 * PADB) + s * 32);
                mma16816(acc[0][j], aH0, b[0], b[1]);
                mma16816(acc[0][j], aH0, b[2], b[3]);
                mma16816(acc[0][j], aL0, b[0], b[1]);
                mma16816(acc[1][j], aH1, b[0], b[1]);
                mma16816(acc[1][j], aH1, b[2], b[3]);
                mma16816(acc[1][j], aL1, b[0], b[1]);
            }
        }

        // ---- bias + SiLU in regs; quad-reduce row partial sums ----
        float s_[2][2] = {{0.f,0.f},{0.f,0.f}}, q_[2][2] = {{0.f,0.f},{0.f,0.f}};
        #pragma unroll
        for (int t = 0; t < 2; ++t)
            #pragma unroll
            for (int j = 0; j < 8; ++j) {
                int c = cbase + j * 8;
                float2 bb = *(float2*)(bS + c);
                float v0 = silu(acc[t][j][0] + bb.x);
                float v1 = silu(acc[t][j][1] + bb.y);
                float v2 = silu(acc[t][j][2] + bb.x);
                float v3 = silu(acc[t][j][3] + bb.y);
                acc[t][j][0] = v0; acc[t][j][1] = v1;
                acc[t][j][2] = v2; acc[t][j][3] = v3;
                s_[t][0] += v0 + v1; q_[t][0] += v0*v0 + v1*v1;
                s_[t][1] += v2 + v3; q_[t][1] += v2*v2 + v3*v3;
            }
        #pragma unroll
        for (int o = 1; o <= 2; o <<= 1) {
            #pragma unroll
            for (int t = 0; t < 2; ++t)
                #pragma unroll
                for (int r = 0; r < 2; ++r) {
                    s_[t][r] += __shfl_xor_sync(0xffffffffu, s_[t][r], o);
                    q_[t][r] += __shfl_xor_sync(0xffffffffu, q_[t][r], o);
                }
        }
        if ((lane & 3) == 0) {
            #pragma unroll
            for (int t = 0; t < 2; ++t) {
                int r = mq * 32 + t * 16 + (lane >> 2);
                psum[r * 4 + nq] = s_[t][0];  psq[r * 4 + nq] = q_[t][0];
                psum[(r + 8) * 4 + nq] = s_[t][1];  psq[(r + 8) * 4 + nq] = q_[t][1];
            }
        }
        __syncthreads();

        // ---- LN params from partials (LDS.128) + direct STG.64 stores ----
        #pragma unroll
        for (int t = 0; t < 2; ++t)
            #pragma unroll
            for (int rr = 0; rr < 2; ++rr) {
                int r = mq * 32 + t * 16 + (lane >> 2) + rr * 8;
                float4 ps = *(float4*)(psum + r * 4);
                float4 pq = *(float4*)(psq + r * 4);
                float mu  = (ps.x + ps.y + ps.z + ps.w) * (1.f / 256.f);
                float var = (pq.x + pq.y + pq.z + pq.w) * (1.f / 256.f) - mu * mu;
                float inv = rsqrtf(var + 1e-5f);
                float* dst = out + ((size_t)grp * MT + r) * DD;
                #pragma unroll
                for (int j = 0; j < 8; ++j) {
                    int c = cbase + j * 8;
                    float2 gg = *(float2*)(gS  + c);
                    float2 be = *(float2*)(btS + c);
                    float2 o2;
                    o2.x = (acc[t][j][rr*2+0] - mu) * inv * gg.x + be.x;
                    o2.y = (acc[t][j][rr*2+1] - mu) * inv * gg.y + be.y;
                    *(float2*)(dst + c) = o2;
                }
            }
    }
}

extern "C" void kernel_launch(void* const* d_in, const int* in_sizes, int n_in,
                              void* d_out, int out_size) {
    const void*  ids     = d_in[0];
    const int*   mask    = (const int*)  d_in[1];
    const int*   gidx    = (const int*)  d_in[2];
    const float* tbl     = (const float*)d_in[3];
    const float* missing = (const float*)d_in[4];
    const float* W       = (const float*)d_in[5];
    const float* b       = (const float*)d_in[6];
    const float* gamma   = (const float*)d_in[7];
    const float* beta    = (const float*)d_in[8];
    float* out = (float*)d_out;

    int nsm = 0;
    cudaDeviceGetAttribute(&nsm, cudaDevAttrMultiProcessorCount, 0);
    if (nsm <= 0) nsm = 148;
    if (nsm > NGRP) nsm = NGRP;

    cudaFuncSetAttribute(fused_tokenizer_kernel,
                         cudaFuncAttributeMaxDynamicSharedMemorySize, SMEM_BYTES);

    detect_kernel<<<1, 32>>>((const unsigned int*)ids);
    fused_tokenizer_kernel<<<nsm, NTHR, SMEM_BYTES>>>(
        ids, mask, gidx, tbl, missing, W, b, gamma, beta, out, nsm);
}

// round 8
// speedup vs baseline: 3.2955x; 1.1615x over previous
#include <cuda_runtime.h>
#include <cuda_bf16.h>
#include <cstdint>

#define BB    8192
#define FF    64
#define VV    1000
#define NTOKN 16
#define GG    4
#define DD    256
#define KK    128
#define SBK   8
#define MT    128          // rows per group = SBK*NTOKN
#define NGRP  (BB / SBK)
#define NTHR  512

#define PADB  272          // bytes per bf16 tile row (136 bf16): conflict-free ldmatrix

// smem byte offsets
#define OFF_BHI  0                         // W hi bf16 [256][136]   69632 B
#define OFF_BLO  69632                     // W lo                   69632 B
#define OFF_AHI  139264                    // x hi bf16 [128][136]   34816 B
#define OFF_ALO  174080                    // x lo                   34816 B
#define OFF_QS0  208896                    // 512 ints (double-buffered q)
#define OFF_QS1  210944
#define OFF_GX   212992                    // 64 ints
#define OFF_BIA  213248                    // 256 floats
#define OFF_GAM  214272
#define OFF_BET  215296
#define OFF_PSUM 216320                    // [128][4] floats
#define OFF_PSQ  218368                    // [128][4] floats
#define OFF_FLAG 220416                    // is64 flag
#define SMEM_BYTES 220448

__device__ __forceinline__ uint32_t smem_u32(const void* p) {
    uint32_t a;
    asm("{ .reg .u64 t; cvta.to.shared.u64 t, %1; cvt.u32.u64 %0, t; }" : "=r"(a) : "l"(p));
    return a;
}
__device__ __forceinline__ void ldm4(uint32_t* r, uint32_t addr) {
    asm volatile("ldmatrix.sync.aligned.m8n8.x4.shared.b16 {%0,%1,%2,%3}, [%4];"
                 : "=r"(r[0]), "=r"(r[1]), "=r"(r[2]), "=r"(r[3]) : "r"(addr));
}
__device__ __forceinline__ void mma16816(float* c, const uint32_t* a,
                                         uint32_t b0, uint32_t b1) {
    asm volatile("mma.sync.aligned.m16n8k16.row.col.f32.bf16.bf16.f32 "
                 "{%0,%1,%2,%3}, {%4,%5,%6,%7}, {%8,%9}, {%0,%1,%2,%3};"
                 : "+f"(c[0]), "+f"(c[1]), "+f"(c[2]), "+f"(c[3])
                 : "r"(a[0]), "r"(a[1]), "r"(a[2]), "r"(a[3]), "r"(b0), "r"(b1));
}
__device__ __forceinline__ void stg_cs2(float* p, float x, float y) {
    asm volatile("st.global.cs.v2.f32 [%0], {%1,%2};" :: "l"(p), "f"(x), "f"(y) : "memory");
}
__device__ __forceinline__ float silu(float v) { return v / (1.f + __expf(-v)); }

__global__ __launch_bounds__(NTHR, 1)
void fused_tokenizer_kernel(const void*  __restrict__ ids_raw,
                            const int*   __restrict__ mask,
                            const int*   __restrict__ gidx,
                            const float* __restrict__ tbl,
                            const float* __restrict__ missing,
                            const float* __restrict__ W,
                            const float* __restrict__ bias,
                            const float* __restrict__ gamma,
                            const float* __restrict__ beta,
                            float*       __restrict__ out,
                            int nblocks)
{
    extern __shared__ char smem[];
    const uint32_t sb = smem_u32(smem);
    int*    gxS  = (int*)   (smem + OFF_GX);
    float*  bS   = (float*) (smem + OFF_BIA);
    float*  gS   = (float*) (smem + OFF_GAM);
    float*  btS  = (float*) (smem + OFF_BET);
    float*  psum = (float*) (smem + OFF_PSUM);
    float*  psq  = (float*) (smem + OFF_PSQ);
    int* qbuf[2] = { (int*)(smem + OFF_QS0), (int*)(smem + OFF_QS1) };

    const int tid  = threadIdx.x;
    const int wid  = tid >> 5;
    const int lane = tid & 31;

    // ---- One-time: split W into bf16 hi/lo padded tiles ----
    for (int i = tid; i < DD * KK; i += NTHR) {
        int n = i >> 7, k = i & 127;
        float w = W[i];
        __nv_bfloat16 hi = __float2bfloat16(w);
        __nv_bfloat16 lo = __float2bfloat16(w - __bfloat162float(hi));
        uint32_t off = (uint32_t)n * PADB + ((uint32_t)k << 1);
        *(__nv_bfloat16*)(smem + OFF_BHI + off) = hi;
        *(__nv_bfloat16*)(smem + OFF_BLO + off) = lo;
    }
    if (tid < NTOKN * GG) gxS[tid] = gidx[tid];
    if (tid < DD) { bS[tid] = bias[tid]; gS[tid] = gamma[tid]; btS[tid] = beta[tid]; }
    // is64 detection: int64 ids < 1000 -> odd 32-bit words all zero
    if (tid < 32) {
        const unsigned int* p = (const unsigned int*)ids_raw;
        int ok = (p[1 + 2*tid] == 0u) & (p[65 + 2*tid] == 0u) &
                 (p[129 + 2*tid] == 0u) & (p[193 + 2*tid] == 0u);
        ok = __all_sync(0xffffffffu, ok);
        if (tid == 0) *(int*)(smem + OFF_FLAG) = ok;
    }
    __syncthreads();
    const int is64 = *(int*)(smem + OFF_FLAG);

    // ---- gather constants: warp owns (tt, mb); lane owns e-pair ----
    const int tt = wid & 1;               // table
    const int mb = wid >> 1;              // m ≡ mb (mod 8)
    const float* gbase = tbl + (size_t)tt * 4096000 + (lane << 1);
    const float* mbase = missing + tt * 4096 + (lane << 1);
    int f0[GG], f1[GG];
    #pragma unroll
    for (int g = 0; g < GG; ++g) {
        f0[g] = gxS[mb * GG + g];         // token n = mb
        f1[g] = gxS[(mb + 8) * GG + g];   // token n = mb+8
    }
    char* aptrH = smem + OFF_AHI + (((tt << 6) + (lane << 1)) << 1);

    // ---- GEMM warp mapping: 32m x 64n tiles (4m x 4n warp grid) ----
    const int mq = wid & 3;
    const int nq = wid >> 2;
    const uint32_t paH = sb + OFF_AHI + (uint32_t)(mq * 32 + (lane & 15)) * PADB
                       + (uint32_t)(lane >> 4) * 16;
    const uint32_t paL = paH + (OFF_ALO - OFF_AHI);
    const int g8 = lane >> 3;
    const uint32_t pb = sb + ((g8 < 2) ? OFF_BHI : OFF_BLO)
                      + (uint32_t)(nq * 64 + (lane & 7)) * PADB
                      + (uint32_t)(g8 & 1) * 16;
    const int cbase = nq * 64 + (lane & 3) * 2;

    // ---- helpers ----
    auto stage_q = [&](int g, int* buf) {
        int gi  = g * (SBK * FF) + tid;
        int idv = is64 ? (int)__ldg((const long long*)ids_raw + gi)
                       : __ldg((const int*)ids_raw + gi);
        int f   = tid & 63;
        buf[tid] = (((f * VV + idv) << 6) << 1) | __ldg(mask + gi);
    };
    auto gather = [&](const int* buf) {
        #pragma unroll 2
        for (int s = 0; s < 8; ++s) {
            const int* q = buf + (s << 6);
            int qm0[GG], qm1[GG];
            #pragma unroll
            for (int g = 0; g < GG; ++g) { qm0[g] = q[f0[g]]; qm1[g] = q[f1[g]]; }
            float2 v0[GG], v1[GG];
            #pragma unroll
            for (int g = 0; g < GG; ++g) {
                v0[g] = __ldg((const float2*)(gbase + (qm0[g] >> 1)));
                v1[g] = __ldg((const float2*)(gbase + (qm1[g] >> 1)));
            }
            float sx0 = 0.f, sy0 = 0.f, sx1 = 0.f, sy1 = 0.f;
            #pragma unroll
            for (int g = 0; g < GG; ++g) {
                sx0 += v0[g].x; sy0 += v0[g].y;
                sx1 += v1[g].x; sy1 += v1[g].y;
                if (qm0[g] & 1) {                       // warp-uniform
                    float2 w2 = __ldg((const float2*)(mbase + (f0[g] << 6)));
                    sx0 += w2.x; sy0 += w2.y;
                }
                if (qm1[g] & 1) {
                    float2 w2 = __ldg((const float2*)(mbase + (f1[g] << 6)));
                    sx1 += w2.x; sy1 += w2.y;
                }
            }
            sx0 *= 0.25f; sy0 *= 0.25f; sx1 *= 0.25f; sy1 *= 0.25f;
            int m0 = mb + (s << 4);
            {
                __nv_bfloat16 h0 = __float2bfloat16(sx0), h1 = __float2bfloat16(sy0);
                __nv_bfloat162 hp = __halves2bfloat162(h0, h1);
                __nv_bfloat162 lp = __floats2bfloat162_rn(sx0 - __bfloat162float(h0),
                                                          sy0 - __bfloat162float(h1));
                char* p = aptrH + (uint32_t)m0 * PADB;
                *(uint32_t*)p = *(uint32_t*)&hp;
                *(uint32_t*)(p + (OFF_ALO - OFF_AHI)) = *(uint32_t*)&lp;
            }
            {
                __nv_bfloat16 h0 = __float2bfloat16(sx1), h1 = __float2bfloat16(sy1);
                __nv_bfloat162 hp = __halves2bfloat162(h0, h1);
                __nv_bfloat162 lp = __floats2bfloat162_rn(sx1 - __bfloat162float(h0),
                                                          sy1 - __bfloat162float(h1));
                char* p = aptrH + (uint32_t)(m0 + 8) * PADB;
                *(uint32_t*)p = *(uint32_t*)&hp;
                *(uint32_t*)(p + (OFF_ALO - OFF_AHI)) = *(uint32_t*)&lp;
            }
        }
    };

    // ---- pipelined prologue ----
    int grp = blockIdx.x;
    stage_q(grp, qbuf[0]);
    __syncthreads();
    gather(qbuf[0]);
    int nxt = grp + nblocks;
    if (nxt < NGRP) stage_q(nxt, qbuf[1]);
    __syncthreads();
    int pb_sel = 1;

    while (true) {
        // ---- GEMM: D = Ahi*Bhi^T + Ahi*Blo^T + Alo*Bhi^T (HMMA, b-prefetch) ----
        float acc[2][8][4];
        #pragma unroll
        for (int t = 0; t < 2; ++t)
            #pragma unroll
            for (int j = 0; j < 8; ++j)
                #pragma unroll
                for (int c = 0; c < 4; ++c) acc[t][j][c] = 0.f;

        #pragma unroll 1
        for (int s = 0; s < 8; ++s) {
            uint32_t aH0[4], aH1[4], aL0[4], aL1[4];
            ldm4(aH0, paH + s * 32);
            ldm4(aH1, paH + 16 * PADB + s * 32);
            ldm4(aL0, paL + s * 32);
            ldm4(aL1, paL + 16 * PADB + s * 32);
            uint32_t bc[4], bn[4];
            ldm4(bc, pb + s * 32);
            #pragma unroll
            for (int j = 0; j < 8; ++j) {
                if (j < 7) ldm4(bn, pb + (uint32_t)(j + 1) * (8 * PADB) + s * 32);
                mma16816(acc[0][j], aH0, bc[0], bc[1]);
                mma16816(acc[0][j], aH0, bc[2], bc[3]);
                mma16816(acc[0][j], aL0, bc[0], bc[1]);
                mma16816(acc[1][j], aH1, bc[0], bc[1]);
                mma16816(acc[1][j], aH1, bc[2], bc[3]);
                mma16816(acc[1][j], aL1, bc[0], bc[1]);
                #pragma unroll
                for (int z = 0; z < 4; ++z) bc[z] = bn[z];
            }
        }

        // ---- bias + SiLU in regs; quad-reduce row partial sums ----
        float s_[2][2] = {{0.f,0.f},{0.f,0.f}}, q_[2][2] = {{0.f,0.f},{0.f,0.f}};
        #pragma unroll
        for (int t = 0; t < 2; ++t)
            #pragma unroll
            for (int j = 0; j < 8; ++j) {
                int c = cbase + j * 8;
                float2 bb = *(float2*)(bS + c);
                float v0 = silu(acc[t][j][0] + bb.x);
                float v1 = silu(acc[t][j][1] + bb.y);
                float v2 = silu(acc[t][j][2] + bb.x);
                float v3 = silu(acc[t][j][3] + bb.y);
                acc[t][j][0] = v0; acc[t][j][1] = v1;
                acc[t][j][2] = v2; acc[t][j][3] = v3;
                s_[t][0] += v0 + v1; q_[t][0] += v0*v0 + v1*v1;
                s_[t][1] += v2 + v3; q_[t][1] += v2*v2 + v3*v3;
            }
        #pragma unroll
        for (int o = 1; o <= 2; o <<= 1) {
            #pragma unroll
            for (int t = 0; t < 2; ++t)
                #pragma unroll
                for (int r = 0; r < 2; ++r) {
                    s_[t][r] += __shfl_xor_sync(0xffffffffu, s_[t][r], o);
                    q_[t][r] += __shfl_xor_sync(0xffffffffu, q_[t][r], o);
                }
        }
        if ((lane & 3) == 0) {
            #pragma unroll
            for (int t = 0; t < 2; ++t) {
                int r = mq * 32 + t * 16 + (lane >> 2);
                psum[r * 4 + nq] = s_[t][0];  psq[r * 4 + nq] = q_[t][0];
                psum[(r + 8) * 4 + nq] = s_[t][1];  psq[(r + 8) * 4 + nq] = q_[t][1];
            }
        }
        __syncthreads();   // psum ready; A tiles free; q(nxt) staged

        // ---- LN params from partials (LDS.128) + direct streaming stores ----
        #pragma unroll
        for (int t = 0; t < 2; ++t)
            #pragma unroll
            for (int rr = 0; rr < 2; ++rr) {
                int r = mq * 32 + t * 16 + (lane >> 2) + rr * 8;
                float4 ps = *(float4*)(psum + r * 4);
                float4 pq = *(float4*)(psq + r * 4);
                float mu  = (ps.x + ps.y + ps.z + ps.w) * (1.f / 256.f);
                float var = (pq.x + pq.y + pq.z + pq.w) * (1.f / 256.f) - mu * mu;
                float inv = rsqrtf(var + 1e-5f);
                float* dst = out + ((size_t)grp * MT + r) * DD;
                #pragma unroll
                for (int j = 0; j < 8; ++j) {
                    int c = cbase + j * 8;
                    float2 gg = *(float2*)(gS  + c);
                    float2 be = *(float2*)(btS + c);
                    stg_cs2(dst + c,
                            (acc[t][j][rr*2+0] - mu) * inv * gg.x + be.x,
                            (acc[t][j][rr*2+1] - mu) * inv * gg.y + be.y);
                }
            }

        // ---- produce next group's A; stage q for group after ----
        int nxt2 = nxt + nblocks;
        if (nxt < NGRP) {
            gather(qbuf[pb_sel]);
            if (nxt2 < NGRP) stage_q(nxt2, qbuf[pb_sel ^ 1]);
        }
        __syncthreads();   // A(nxt) ready; q(nxt2) staged
        if (nxt >= NGRP) break;
        grp = nxt; nxt = nxt2; pb_sel ^= 1;
    }
}

extern "C" void kernel_launch(void* const* d_in, const int* in_sizes, int n_in,
                              void* d_out, int out_size) {
    const void*  ids     = d_in[0];
    const int*   mask    = (const int*)  d_in[1];
    const int*   gidx    = (const int*)  d_in[2];
    const float* tbl     = (const float*)d_in[3];
    const float* missing = (const float*)d_in[4];
    const float* W       = (const float*)d_in[5];
    const float* b       = (const float*)d_in[6];
    const float* gamma   = (const float*)d_in[7];
    const float* beta    = (const float*)d_in[8];
    float* out = (float*)d_out;

    int nsm = 0;
    cudaDeviceGetAttribute(&nsm, cudaDevAttrMultiProcessorCount, 0);
    if (nsm <= 0) nsm = 148;
    if (nsm > NGRP) nsm = NGRP;

    cudaFuncSetAttribute(fused_tokenizer_kernel,
                         cudaFuncAttributeMaxDynamicSharedMemorySize, SMEM_BYTES);

    fused_tokenizer_kernel<<<nsm, NTHR, SMEM_BYTES>>>(
        ids, mask, gidx, tbl, missing, W, b, gamma, beta, out, nsm);
}

// round 9
// speedup vs baseline: 3.3100x; 1.0044x over previous
#include <cuda_runtime.h>
#include <cuda_bf16.h>
#include <cstdint>

#define BB    8192
#define FF    64
#define VV    1000
#define NTOKN 16
#define GG    4
#define DD    256
#define KK    128
#define SBK   8
#define MT    128          // rows per group = SBK*NTOKN
#define NGRP  (BB / SBK)
#define NTHR  512

#define PADB  272          // bytes per bf16 tile row (136 bf16): conflict-free ldmatrix

// smem byte offsets
#define OFF_BHI  0                         // W hi bf16 [256][136]   69632 B
#define OFF_BLO  69632                     // W lo                   69632 B
#define OFF_AHI  139264                    // x hi bf16 [128][136]   34816 B
#define OFF_ALO  174080                    // x lo                   34816 B
#define OFF_QS0  208896                    // 512 ints (double-buffered q)
#define OFF_QS1  210944
#define OFF_GX   212992                    // 64 ints
#define OFF_BIA  213248                    // 256 floats
#define OFF_GAM  214272
#define OFF_BET  215296
#define OFF_PSUM 216320                    // [128][4] floats
#define OFF_PSQ  218368                    // [128][4] floats
#define OFF_FLAG 220416                    // is64 flag
#define SMEM_BYTES 220448

__device__ __forceinline__ uint32_t smem_u32(const void* p) {
    uint32_t a;
    asm("{ .reg .u64 t; cvta.to.shared.u64 t, %1; cvt.u32.u64 %0, t; }" : "=r"(a) : "l"(p));
    return a;
}
__device__ __forceinline__ void ldm4(uint32_t* r, uint32_t addr) {
    asm volatile("ldmatrix.sync.aligned.m8n8.x4.shared.b16 {%0,%1,%2,%3}, [%4];"
                 : "=r"(r[0]), "=r"(r[1]), "=r"(r[2]), "=r"(r[3]) : "r"(addr));
}
__device__ __forceinline__ void mma16816(float* c, const uint32_t* a,
                                         uint32_t b0, uint32_t b1) {
    asm volatile("mma.sync.aligned.m16n8k16.row.col.f32.bf16.bf16.f32 "
                 "{%0,%1,%2,%3}, {%4,%5,%6,%7}, {%8,%9}, {%0,%1,%2,%3};"
                 : "+f"(c[0]), "+f"(c[1]), "+f"(c[2]), "+f"(c[3])
                 : "r"(a[0]), "r"(a[1]), "r"(a[2]), "r"(a[3]), "r"(b0), "r"(b1));
}
__device__ __forceinline__ void stg_cs2(float* p, float x, float y) {
    asm volatile("st.global.cs.v2.f32 [%0], {%1,%2};" :: "l"(p), "f"(x), "f"(y) : "memory");
}
__device__ __forceinline__ float silu(float v) { return v / (1.f + __expf(-v)); }

__global__ __launch_bounds__(NTHR, 1)
void fused_tokenizer_kernel(const void*  __restrict__ ids_raw,
                            const int*   __restrict__ mask,
                            const int*   __restrict__ gidx,
                            const float* __restrict__ tbl,
                            const float* __restrict__ missing,
                            const float* __restrict__ W,
                            const float* __restrict__ bias,
                            const float* __restrict__ gamma,
                            const float* __restrict__ beta,
                            float*       __restrict__ out,
                            int nblocks)
{
    extern __shared__ char smem[];
    const uint32_t sb = smem_u32(smem);
    int*    gxS  = (int*)   (smem + OFF_GX);
    float*  bS   = (float*) (smem + OFF_BIA);
    float*  gS   = (float*) (smem + OFF_GAM);
    float*  btS  = (float*) (smem + OFF_BET);
    float*  psum = (float*) (smem + OFF_PSUM);
    float*  psq  = (float*) (smem + OFF_PSQ);
    int* qbuf[2] = { (int*)(smem + OFF_QS0), (int*)(smem + OFF_QS1) };

    const int tid  = threadIdx.x;
    const int wid  = tid >> 5;
    const int lane = tid & 31;

    // ---- One-time: split W into bf16 hi/lo padded tiles ----
    for (int i = tid; i < DD * KK; i += NTHR) {
        int n = i >> 7, k = i & 127;
        float w = W[i];
        __nv_bfloat16 hi = __float2bfloat16(w);
        __nv_bfloat16 lo = __float2bfloat16(w - __bfloat162float(hi));
        uint32_t off = (uint32_t)n * PADB + ((uint32_t)k << 1);
        *(__nv_bfloat16*)(smem + OFF_BHI + off) = hi;
        *(__nv_bfloat16*)(smem + OFF_BLO + off) = lo;
    }
    if (tid < NTOKN * GG) gxS[tid] = gidx[tid];
    if (tid < DD) { bS[tid] = bias[tid]; gS[tid] = gamma[tid]; btS[tid] = beta[tid]; }
    // is64 detection: int64 ids < 1000 -> odd 32-bit words all zero
    if (tid < 32) {
        const unsigned int* p = (const unsigned int*)ids_raw;
        int ok = (p[1 + 2*tid] == 0u) & (p[65 + 2*tid] == 0u) &
                 (p[129 + 2*tid] == 0u) & (p[193 + 2*tid] == 0u);
        ok = __all_sync(0xffffffffu, ok);
        if (tid == 0) *(int*)(smem + OFF_FLAG) = ok;
    }
    __syncthreads();
    const int is64 = *(int*)(smem + OFF_FLAG);

    // ---- gather constants: warp owns (tt, mb); lane = (token-parity, e-quad) ----
    const int tt  = wid & 1;              // table half (k = tt*64 + eq*4 + {0..3})
    const int mb  = wid >> 1;             // rows m ≡ mb (mod 8)
    const int t01 = lane >> 4;            // token parity: row = mb + s*16 + t01*8
    const int eq  = lane & 15;            // e-quad
    const int ntok = mb + t01 * 8;        // this lane's token (fixed!)
    int fL[GG];
    #pragma unroll
    for (int g = 0; g < GG; ++g) fL[g] = gxS[ntok * GG + g];
    const float* gbase = tbl + (size_t)tt * 4096000 + (eq << 2);
    // missing-emb vectors are group-invariant per lane: load ONCE
    float4 wmiss[GG];
    #pragma unroll
    for (int g = 0; g < GG; ++g)
        wmiss[g] = __ldg((const float4*)(missing + tt * 4096 + (fL[g] << 6) + (eq << 2)));
    char* aptrH = smem + OFF_AHI + tt * 128 + eq * 8;   // + m*PADB per row

    // ---- GEMM warp mapping: 32m x 64n tiles (4m x 4n warp grid) ----
    const int mq = wid & 3;
    const int nq = wid >> 2;
    const uint32_t paH = sb + OFF_AHI + (uint32_t)(mq * 32 + (lane & 15)) * PADB
                       + (uint32_t)(lane >> 4) * 16;
    const uint32_t paL = paH + (OFF_ALO - OFF_AHI);
    const int g8 = lane >> 3;
    const uint32_t pb = sb + ((g8 < 2) ? OFF_BHI : OFF_BLO)
                      + (uint32_t)(nq * 64 + (lane & 7)) * PADB
                      + (uint32_t)(g8 & 1) * 16;
    const int cbase = nq * 64 + (lane & 3) * 2;

    // ---- helpers ----
    auto stage_q = [&](int g, int* buf) {
        int gi  = g * (SBK * FF) + tid;
        int idv = is64 ? (int)__ldg((const long long*)ids_raw + gi)
                       : __ldg((const int*)ids_raw + gi);
        int f   = tid & 63;
        buf[tid] = (((f * VV + idv) << 6) << 1) | __ldg(mask + gi);
    };
    auto gather = [&](const int* buf) {
        #pragma unroll 4
        for (int s = 0; s < 8; ++s) {
            const int* q = buf + (s << 6);
            int qm[GG];
            #pragma unroll
            for (int g = 0; g < GG; ++g) qm[g] = q[fL[g]];
            float4 v[GG];
            #pragma unroll
            for (int g = 0; g < GG; ++g)
                v[g] = __ldg((const float4*)(gbase + (qm[g] >> 1)));
            float x0 = 0.f, x1 = 0.f, x2 = 0.f, x3 = 0.f;
            #pragma unroll
            for (int g = 0; g < GG; ++g) {
                float mk = (float)(qm[g] & 1);
                x0 += v[g].x + mk * wmiss[g].x;
                x1 += v[g].y + mk * wmiss[g].y;
                x2 += v[g].z + mk * wmiss[g].z;
                x3 += v[g].w + mk * wmiss[g].w;
            }
            x0 *= 0.25f; x1 *= 0.25f; x2 *= 0.25f; x3 *= 0.25f;
            __nv_bfloat16 h0 = __float2bfloat16(x0), h1 = __float2bfloat16(x1);
            __nv_bfloat16 h2 = __float2bfloat16(x2), h3 = __float2bfloat16(x3);
            __nv_bfloat162 hp0 = __halves2bfloat162(h0, h1);
            __nv_bfloat162 hp1 = __halves2bfloat162(h2, h3);
            __nv_bfloat162 lp0 = __floats2bfloat162_rn(x0 - __bfloat162float(h0),
                                                       x1 - __bfloat162float(h1));
            __nv_bfloat162 lp1 = __floats2bfloat162_rn(x2 - __bfloat162float(h2),
                                                       x3 - __bfloat162float(h3));
            int m = mb + (s << 4) + (t01 << 3);
            char* p = aptrH + (uint32_t)m * PADB;
            uint2 hv = make_uint2(*(uint32_t*)&hp0, *(uint32_t*)&hp1);
            uint2 lv = make_uint2(*(uint32_t*)&lp0, *(uint32_t*)&lp1);
            *(uint2*)p = hv;
            *(uint2*)(p + (OFF_ALO - OFF_AHI)) = lv;
        }
    };

    // ---- pipelined prologue ----
    int grp = blockIdx.x;
    stage_q(grp, qbuf[0]);
    __syncthreads();
    gather(qbuf[0]);
    int nxt = grp + nblocks;
    if (nxt < NGRP) stage_q(nxt, qbuf[1]);
    __syncthreads();
    int pb_sel = 1;

    while (true) {
        // ---- GEMM: D = Ahi*Bhi^T + Ahi*Blo^T + Alo*Bhi^T (HMMA, b-prefetch) ----
        float acc[2][8][4];
        #pragma unroll
        for (int t = 0; t < 2; ++t)
            #pragma unroll
            for (int j = 0; j < 8; ++j)
                #pragma unroll
                for (int c = 0; c < 4; ++c) acc[t][j][c] = 0.f;

        #pragma unroll 1
        for (int s = 0; s < 8; ++s) {
            uint32_t aH0[4], aH1[4], aL0[4], aL1[4];
            ldm4(aH0, paH + s * 32);
            ldm4(aH1, paH + 16 * PADB + s * 32);
            ldm4(aL0, paL + s * 32);
            ldm4(aL1, paL + 16 * PADB + s * 32);
            uint32_t bc[4], bn[4];
            ldm4(bc, pb + s * 32);
            #pragma unroll
            for (int j = 0; j < 8; ++j) {
                if (j < 7) ldm4(bn, pb + (uint32_t)(j + 1) * (8 * PADB) + s * 32);
                mma16816(acc[0][j], aH0, bc[0], bc[1]);
                mma16816(acc[0][j], aH0, bc[2], bc[3]);
                mma16816(acc[0][j], aL0, bc[0], bc[1]);
                mma16816(acc[1][j], aH1, bc[0], bc[1]);
                mma16816(acc[1][j], aH1, bc[2], bc[3]);
                mma16816(acc[1][j], aL1, bc[0], bc[1]);
                #pragma unroll
                for (int z = 0; z < 4; ++z) bc[z] = bn[z];
            }
        }

        // ---- bias + SiLU in regs; quad-reduce row partial sums ----
        float s_[2][2] = {{0.f,0.f},{0.f,0.f}}, q_[2][2] = {{0.f,0.f},{0.f,0.f}};
        #pragma unroll
        for (int t = 0; t < 2; ++t)
            #pragma unroll
            for (int j = 0; j < 8; ++j) {
                int c = cbase + j * 8;
                float2 bb = *(float2*)(bS + c);
                float v0 = silu(acc[t][j][0] + bb.x);
                float v1 = silu(acc[t][j][1] + bb.y);
                float v2 = silu(acc[t][j][2] + bb.x);
                float v3 = silu(acc[t][j][3] + bb.y);
                acc[t][j][0] = v0; acc[t][j][1] = v1;
                acc[t][j][2] = v2; acc[t][j][3] = v3;
                s_[t][0] += v0 + v1; q_[t][0] += v0*v0 + v1*v1;
                s_[t][1] += v2 + v3; q_[t][1] += v2*v2 + v3*v3;
            }
        #pragma unroll
        for (int o = 1; o <= 2; o <<= 1) {
            #pragma unroll
            for (int t = 0; t < 2; ++t)
                #pragma unroll
                for (int r = 0; r < 2; ++r) {
                    s_[t][r] += __shfl_xor_sync(0xffffffffu, s_[t][r], o);
                    q_[t][r] += __shfl_xor_sync(0xffffffffu, q_[t][r], o);
                }
        }
        if ((lane & 3) == 0) {
            #pragma unroll
            for (int t = 0; t < 2; ++t) {
                int r = mq * 32 + t * 16 + (lane >> 2);
                psum[r * 4 + nq] = s_[t][0];  psq[r * 4 + nq] = q_[t][0];
                psum[(r + 8) * 4 + nq] = s_[t][1];  psq[(r + 8) * 4 + nq] = q_[t][1];
            }
        }
        __syncthreads();   // psum ready; A tiles free; q(nxt) staged

        // ---- gather(next) issued FIRST so its LDG latency hides under the
        //      LN epilogue below (single straight-line region, no barrier) ----
        int nxt2 = nxt + nblocks;
        if (nxt < NGRP) gather(qbuf[pb_sel]);

        // ---- LN params from partials (LDS.128) + direct streaming stores ----
        #pragma unroll
        for (int t = 0; t < 2; ++t)
            #pragma unroll
            for (int rr = 0; rr < 2; ++rr) {
                int r = mq * 32 + t * 16 + (lane >> 2) + rr * 8;
                float4 ps = *(float4*)(psum + r * 4);
                float4 pq = *(float4*)(psq + r * 4);
                float mu  = (ps.x + ps.y + ps.z + ps.w) * (1.f / 256.f);
                float var = (pq.x + pq.y + pq.z + pq.w) * (1.f / 256.f) - mu * mu;
                float inv = rsqrtf(var + 1e-5f);
                float* dst = out + ((size_t)grp * MT + r) * DD;
                #pragma unroll
                for (int j = 0; j < 8; ++j) {
                    int c = cbase + j * 8;
                    float2 gg = *(float2*)(gS  + c);
                    float2 be = *(float2*)(btS + c);
                    stg_cs2(dst + c,
                            (acc[t][j][rr*2+0] - mu) * inv * gg.x + be.x,
                            (acc[t][j][rr*2+1] - mu) * inv * gg.y + be.y);
                }
            }

        if (nxt < NGRP && nxt2 < NGRP) stage_q(nxt2, qbuf[pb_sel ^ 1]);
        __syncthreads();   // A(nxt) ready; q(nxt2) staged
        if (nxt >= NGRP) break;
        grp = nxt; nxt = nxt2; pb_sel ^= 1;
    }
}

extern "C" void kernel_launch(void* const* d_in, const int* in_sizes, int n_in,
                              void* d_out, int out_size) {
    const void*  ids     = d_in[0];
    const int*   mask    = (const int*)  d_in[1];
    const int*   gidx    = (const int*)  d_in[2];
    const float* tbl     = (const float*)d_in[3];
    const float* missing = (const float*)d_in[4];
    const float* W       = (const float*)d_in[5];
    const float* b       = (const float*)d_in[6];
    const float* gamma   = (const float*)d_in[7];
    const float* beta    = (const float*)d_in[8];
    float* out = (float*)d_out;

    int nsm = 0;
    cudaDeviceGetAttribute(&nsm, cudaDevAttrMultiProcessorCount, 0);
    if (nsm <= 0) nsm = 148;
    if (nsm > NGRP) nsm = NGRP;

    cudaFuncSetAttribute(fused_tokenizer_kernel,
                         cudaFuncAttributeMaxDynamicSharedMemorySize, SMEM_BYTES);

    fused_tokenizer_kernel<<<nsm, NTHR, SMEM_BYTES>>>(
        ids, mask, gidx, tbl, missing, W, b, gamma, beta, out, nsm);
}

// round 10
// speedup vs baseline: 3.7396x; 1.1298x over previous
#include <cuda_runtime.h>
#include <cuda_fp16.h>
#include <cstdint>

#define BB    8192
#define FF    64
#define VV    1000
#define NTOKN 16
#define GG    4
#define DD    256
#define KK    128
#define SBK   8
#define MT    128          // rows per group = SBK*NTOKN
#define NGRP  (BB / SBK)
#define NTHR  512

#define PADB  272          // bytes per fp16 tile row (136 halves): conflict-free ldmatrix

// smem byte offsets
#define OFF_BHI  0                         // W hi fp16 [256][136]   69632 B
#define OFF_BLO  69632                     // W lo fp16              69632 B
#define OFF_AHI  139264                    // x  fp16 [128][136]     34816 B
#define OFF_QS0  174080                    // 512 ints (double-buffered q)
#define OFF_QS1  176128
#define OFF_GX   178176                    // 64 ints
#define OFF_BIA  178432                    // 256 floats
#define OFF_GAM  179456
#define OFF_BET  180480
#define OFF_PSUM 181504                    // [128][4] floats
#define OFF_PSQ  183552                    // [128][4] floats
#define OFF_FLAG 185600                    // is64 flag
#define SMEM_BYTES 185632

__device__ __forceinline__ uint32_t smem_u32(const void* p) {
    uint32_t a;
    asm("{ .reg .u64 t; cvta.to.shared.u64 t, %1; cvt.u32.u64 %0, t; }" : "=r"(a) : "l"(p));
    return a;
}
__device__ __forceinline__ void ldm4(uint32_t* r, uint32_t addr) {
    asm volatile("ldmatrix.sync.aligned.m8n8.x4.shared.b16 {%0,%1,%2,%3}, [%4];"
                 : "=r"(r[0]), "=r"(r[1]), "=r"(r[2]), "=r"(r[3]) : "r"(addr));
}
__device__ __forceinline__ void mma16816(float* c, const uint32_t* a,
                                         uint32_t b0, uint32_t b1) {
    asm volatile("mma.sync.aligned.m16n8k16.row.col.f32.f16.f16.f32 "
                 "{%0,%1,%2,%3}, {%4,%5,%6,%7}, {%8,%9}, {%0,%1,%2,%3};"
                 : "+f"(c[0]), "+f"(c[1]), "+f"(c[2]), "+f"(c[3])
                 : "r"(a[0]), "r"(a[1]), "r"(a[2]), "r"(a[3]), "r"(b0), "r"(b1));
}
__device__ __forceinline__ void stg_cs2(float* p, float x, float y) {
    asm volatile("st.global.cs.v2.f32 [%0], {%1,%2};" :: "l"(p), "f"(x), "f"(y) : "memory");
}
__device__ __forceinline__ float silu(float v) { return v / (1.f + __expf(-v)); }

__global__ __launch_bounds__(NTHR, 1)
void fused_tokenizer_kernel(const void*  __restrict__ ids_raw,
                            const int*   __restrict__ mask,
                            const int*   __restrict__ gidx,
                            const float* __restrict__ tbl,
                            const float* __restrict__ missing,
                            const float* __restrict__ W,
                            const float* __restrict__ bias,
                            const float* __restrict__ gamma,
                            const float* __restrict__ beta,
                            float*       __restrict__ out,
                            int nblocks)
{
    extern __shared__ char smem[];
    const uint32_t sb = smem_u32(smem);
    int*    gxS  = (int*)   (smem + OFF_GX);
    float*  bS   = (float*) (smem + OFF_BIA);
    float*  gS   = (float*) (smem + OFF_GAM);
    float*  btS  = (float*) (smem + OFF_BET);
    float*  psum = (float*) (smem + OFF_PSUM);
    float*  psq  = (float*) (smem + OFF_PSQ);
    int* qbuf[2] = { (int*)(smem + OFF_QS0), (int*)(smem + OFF_QS1) };

    const int tid  = threadIdx.x;
    const int wid  = tid >> 5;
    const int lane = tid & 31;

    // ---- One-time: split W into fp16 hi/lo padded tiles (22-bit coverage) ----
    for (int i = tid; i < DD * KK; i += NTHR) {
        int n = i >> 7, k = i & 127;
        float w = W[i];
        __half hi = __float2half_rn(w);
        __half lo = __float2half_rn(w - __half2float(hi));
        uint32_t off = (uint32_t)n * PADB + ((uint32_t)k << 1);
        *(__half*)(smem + OFF_BHI + off) = hi;
        *(__half*)(smem + OFF_BLO + off) = lo;
    }
    if (tid < NTOKN * GG) gxS[tid] = gidx[tid];
    if (tid < DD) { bS[tid] = bias[tid]; gS[tid] = gamma[tid]; btS[tid] = beta[tid]; }
    // is64 detection: int64 ids < 1000 -> odd 32-bit words all zero
    if (tid < 32) {
        const unsigned int* p = (const unsigned int*)ids_raw;
        int ok = (p[1 + 2*tid] == 0u) & (p[65 + 2*tid] == 0u) &
                 (p[129 + 2*tid] == 0u) & (p[193 + 2*tid] == 0u);
        ok = __all_sync(0xffffffffu, ok);
        if (tid == 0) *(int*)(smem + OFF_FLAG) = ok;
    }
    __syncthreads();
    const int is64 = *(int*)(smem + OFF_FLAG);

    // ---- gather constants: warp owns (tt, mb); lane = (token-parity, e-quad) ----
    const int tt  = wid & 1;              // table half (k = tt*64 + eq*4 + {0..3})
    const int mb  = wid >> 1;             // rows m ≡ mb (mod 8)
    const int t01 = lane >> 4;            // token parity: row = mb + s*16 + t01*8
    const int eq  = lane & 15;            // e-quad
    const int ntok = mb + t01 * 8;        // this lane's token (fixed!)
    int fL[GG];
    #pragma unroll
    for (int g = 0; g < GG; ++g) fL[g] = gxS[ntok * GG + g];
    const float* gbase = tbl + (size_t)tt * 4096000 + (eq << 2);
    // missing-emb vectors are group-invariant per lane: load ONCE
    float4 wmiss[GG];
    #pragma unroll
    for (int g = 0; g < GG; ++g)
        wmiss[g] = __ldg((const float4*)(missing + tt * 4096 + (fL[g] << 6) + (eq << 2)));
    char* aptrH = smem + OFF_AHI + tt * 128 + eq * 8;   // + m*PADB per row

    // ---- GEMM warp mapping: 32m x 64n tiles (4m x 4n warp grid) ----
    const int mq = wid & 3;
    const int nq = wid >> 2;
    const uint32_t paH = sb + OFF_AHI + (uint32_t)(mq * 32 + (lane & 15)) * PADB
                       + (uint32_t)(lane >> 4) * 16;
    const int g8 = lane >> 3;
    const uint32_t pb = sb + ((g8 < 2) ? OFF_BHI : OFF_BLO)
                      + (uint32_t)(nq * 64 + (lane & 7)) * PADB
                      + (uint32_t)(g8 & 1) * 16;
    const int cbase = nq * 64 + (lane & 3) * 2;

    // ---- helpers ----
    auto stage_q = [&](int g, int* buf) {
        int gi  = g * (SBK * FF) + tid;
        int idv = is64 ? (int)__ldg((const long long*)ids_raw + gi)
                       : __ldg((const int*)ids_raw + gi);
        int f   = tid & 63;
        buf[tid] = (((f * VV + idv) << 6) << 1) | __ldg(mask + gi);
    };
    auto gather = [&](const int* buf) {
        #pragma unroll 4
        for (int s = 0; s < 8; ++s) {
            const int* q = buf + (s << 6);
            int qm[GG];
            #pragma unroll
            for (int g = 0; g < GG; ++g) qm[g] = q[fL[g]];
            float4 v[GG];
            #pragma unroll
            for (int g = 0; g < GG; ++g)
                v[g] = __ldg((const float4*)(gbase + (qm[g] >> 1)));
            float x0 = 0.f, x1 = 0.f, x2 = 0.f, x3 = 0.f;
            #pragma unroll
            for (int g = 0; g < GG; ++g) {
                float mk = (float)(qm[g] & 1);
                x0 += v[g].x + mk * wmiss[g].x;
                x1 += v[g].y + mk * wmiss[g].y;
                x2 += v[g].z + mk * wmiss[g].z;
                x3 += v[g].w + mk * wmiss[g].w;
            }
            __half2 hp0 = __floats2half2_rn(x0 * 0.25f, x1 * 0.25f);
            __half2 hp1 = __floats2half2_rn(x2 * 0.25f, x3 * 0.25f);
            int m = mb + (s << 4) + (t01 << 3);
            *(uint2*)(aptrH + (uint32_t)m * PADB) =
                make_uint2(*(uint32_t*)&hp0, *(uint32_t*)&hp1);
        }
    };

    // ---- pipelined prologue ----
    int grp = blockIdx.x;
    stage_q(grp, qbuf[0]);
    __syncthreads();
    gather(qbuf[0]);
    int nxt = grp + nblocks;
    if (nxt < NGRP) stage_q(nxt, qbuf[1]);
    __syncthreads();
    int pb_sel = 1;

    while (true) {
        // ---- GEMM: D = A*Bhi^T + A*Blo^T (fp16 HMMA, b-prefetch) ----
        float acc[2][8][4];
        #pragma unroll
        for (int t = 0; t < 2; ++t)
            #pragma unroll
            for (int j = 0; j < 8; ++j)
                #pragma unroll
                for (int c = 0; c < 4; ++c) acc[t][j][c] = 0.f;

        #pragma unroll 1
        for (int s = 0; s < 8; ++s) {
            uint32_t aH0[4], aH1[4];
            ldm4(aH0, paH + s * 32);
            ldm4(aH1, paH + 16 * PADB + s * 32);
            uint32_t bc[4], bn[4];
            ldm4(bc, pb + s * 32);
            #pragma unroll
            for (int j = 0; j < 8; ++j) {
                if (j < 7) ldm4(bn, pb + (uint32_t)(j + 1) * (8 * PADB) + s * 32);
                mma16816(acc[0][j], aH0, bc[0], bc[1]);   // A * W_hi
                mma16816(acc[0][j], aH0, bc[2], bc[3]);   // A * W_lo
                mma16816(acc[1][j], aH1, bc[0], bc[1]);
                mma16816(acc[1][j], aH1, bc[2], bc[3]);
                #pragma unroll
                for (int z = 0; z < 4; ++z) bc[z] = bn[z];
            }
        }

        // ---- bias + SiLU in regs; quad-reduce row partial sums ----
        float s_[2][2] = {{0.f,0.f},{0.f,0.f}}, q_[2][2] = {{0.f,0.f},{0.f,0.f}};
        #pragma unroll
        for (int t = 0; t < 2; ++t)
            #pragma unroll
            for (int j = 0; j < 8; ++j) {
                int c = cbase + j * 8;
                float2 bb = *(float2*)(bS + c);
                float v0 = silu(acc[t][j][0] + bb.x);
                float v1 = silu(acc[t][j][1] + bb.y);
                float v2 = silu(acc[t][j][2] + bb.x);
                float v3 = silu(acc[t][j][3] + bb.y);
                acc[t][j][0] = v0; acc[t][j][1] = v1;
                acc[t][j][2] = v2; acc[t][j][3] = v3;
                s_[t][0] += v0 + v1; q_[t][0] += v0*v0 + v1*v1;
                s_[t][1] += v2 + v3; q_[t][1] += v2*v2 + v3*v3;
            }
        #pragma unroll
        for (int o = 1; o <= 2; o <<= 1) {
            #pragma unroll
            for (int t = 0; t < 2; ++t)
                #pragma unroll
                for (int r = 0; r < 2; ++r) {
                    s_[t][r] += __shfl_xor_sync(0xffffffffu, s_[t][r], o);
                    q_[t][r] += __shfl_xor_sync(0xffffffffu, q_[t][r], o);
                }
        }
        if ((lane & 3) == 0) {
            #pragma unroll
            for (int t = 0; t < 2; ++t) {
                int r = mq * 32 + t * 16 + (lane >> 2);
                psum[r * 4 + nq] = s_[t][0];  psq[r * 4 + nq] = q_[t][0];
                psum[(r + 8) * 4 + nq] = s_[t][1];  psq[(r + 8) * 4 + nq] = q_[t][1];
            }
        }
        __syncthreads();   // psum ready; A tiles free; q(nxt) staged

        // ---- gather(next) issued FIRST so its LDG latency hides under the
        //      LN epilogue below (single straight-line region, no barrier) ----
        int nxt2 = nxt + nblocks;
        if (nxt < NGRP) gather(qbuf[pb_sel]);

        // ---- LN params from partials (LDS.128) + direct streaming stores ----
        #pragma unroll
        for (int t = 0; t < 2; ++t)
            #pragma unroll
            for (int rr = 0; rr < 2; ++rr) {
                int r = mq * 32 + t * 16 + (lane >> 2) + rr * 8;
                float4 ps = *(float4*)(psum + r * 4);
                float4 pq = *(float4*)(psq + r * 4);
                float mu  = (ps.x + ps.y + ps.z + ps.w) * (1.f / 256.f);
                float var = (pq.x + pq.y + pq.z + pq.w) * (1.f / 256.f) - mu * mu;
                float inv = rsqrtf(var + 1e-5f);
                float* dst = out + ((size_t)grp * MT + r) * DD;
                #pragma unroll
                for (int j = 0; j < 8; ++j) {
                    int c = cbase + j * 8;
                    float2 gg = *(float2*)(gS  + c);
                    float2 be = *(float2*)(btS + c);
                    stg_cs2(dst + c,
                            (acc[t][j][rr*2+0] - mu) * inv * gg.x + be.x,
                            (acc[t][j][rr*2+1] - mu) * inv * gg.y + be.y);
                }
            }

        if (nxt < NGRP && nxt2 < NGRP) stage_q(nxt2, qbuf[pb_sel ^ 1]);
        __syncthreads();   // A(nxt) ready; q(nxt2) staged
        if (nxt >= NGRP) break;
        grp = nxt; nxt = nxt2; pb_sel ^= 1;
    }
}

extern "C" void kernel_launch(void* const* d_in, const int* in_sizes, int n_in,
                              void* d_out, int out_size) {
    const void*  ids     = d_in[0];
    const int*   mask    = (const int*)  d_in[1];
    const int*   gidx    = (const int*)  d_in[2];
    const float* tbl     = (const float*)d_in[3];
    const float* missing = (const float*)d_in[4];
    const float* W       = (const float*)d_in[5];
    const float* b       = (const float*)d_in[6];
    const float* gamma   = (const float*)d_in[7];
    const float* beta    = (const float*)d_in[8];
    float* out = (float*)d_out;

    int nsm = 0;
    cudaDeviceGetAttribute(&nsm, cudaDevAttrMultiProcessorCount, 0);
    if (nsm <= 0) nsm = 148;
    if (nsm > NGRP) nsm = NGRP;

    cudaFuncSetAttribute(fused_tokenizer_kernel,
                         cudaFuncAttributeMaxDynamicSharedMemorySize, SMEM_BYTES);

    fused_tokenizer_kernel<<<nsm, NTHR, SMEM_BYTES>>>(
        ids, mask, gidx, tbl, missing, W, b, gamma, beta, out, nsm);
}

// round 12
// speedup vs baseline: 3.9689x; 1.0613x over previous
#include <cuda_runtime.h>
#include <cuda_fp16.h>
#include <cstdint>

#define BB    8192
#define FF    64
#define VV    1000
#define NTOKN 16
#define GG    4
#define DD    256
#define KK    128
#define SBK   8
#define MT    128          // rows per group = SBK*NTOKN
#define NGRP  (BB / SBK)
#define NTHR  512

#define PADB  272          // bytes per fp16 tile row (136 halves): conflict-free ldmatrix
#define ASZ   34816        // one A tile (128 * PADB)

// smem byte offsets
#define OFF_BHI  0                         // W hi fp16 [256][136]   69632 B
#define OFF_BLO  69632                     // W lo fp16              69632 B
#define OFF_A0   139264                    // x fp16 tile, buffer 0  34816 B
#define OFF_A1   174080                    // x fp16 tile, buffer 1  34816 B
#define OFF_QS0  208896                    // 512 ints (double-buffered q)
#define OFF_QS1  210944
#define OFF_GX   212992                    // 64 ints
#define OFF_BIA  213248                    // 256 floats
#define OFF_GAM  214272
#define OFF_BET  215296
#define OFF_PSUM 216320                    // [128][4] floats
#define OFF_PSQ  218368                    // [128][4] floats
#define OFF_FLAG 220416                    // is64 flag
#define SMEM_BYTES 220448

__device__ __forceinline__ uint32_t smem_u32(const void* p) {
    uint32_t a;
    asm("{ .reg .u64 t; cvta.to.shared.u64 t, %1; cvt.u32.u64 %0, t; }" : "=r"(a) : "l"(p));
    return a;
}
__device__ __forceinline__ void ldm4(uint32_t* r, uint32_t addr) {
    asm volatile("ldmatrix.sync.aligned.m8n8.x4.shared.b16 {%0,%1,%2,%3}, [%4];"
                 : "=r"(r[0]), "=r"(r[1]), "=r"(r[2]), "=r"(r[3]) : "r"(addr));
}
__device__ __forceinline__ void mma16816(float* c, const uint32_t* a,
                                         uint32_t b0, uint32_t b1) {
    asm volatile("mma.sync.aligned.m16n8k16.row.col.f32.f16.f16.f32 "
                 "{%0,%1,%2,%3}, {%4,%5,%6,%7}, {%8,%9}, {%0,%1,%2,%3};"
                 : "+f"(c[0]), "+f"(c[1]), "+f"(c[2]), "+f"(c[3])
                 : "r"(a[0]), "r"(a[1]), "r"(a[2]), "r"(a[3]), "r"(b0), "r"(b1));
}
__device__ __forceinline__ void stg_cs2(float* p, float x, float y) {
    asm volatile("st.global.cs.v2.f32 [%0], {%1,%2};" :: "l"(p), "f"(x), "f"(y) : "memory");
}
__device__ __forceinline__ float silu(float v) { return v / (1.f + __expf(-v)); }

__global__ __launch_bounds__(NTHR, 1)
void fused_tokenizer_kernel(const void*  __restrict__ ids_raw,
                            const int*   __restrict__ mask,
                            const int*   __restrict__ gidx,
                            const float* __restrict__ tbl,
                            const float* __restrict__ missing,
                            const float* __restrict__ W,
                            const float* __restrict__ bias,
                            const float* __restrict__ gamma,
                            const float* __restrict__ beta,
                            float*       __restrict__ out,
                            int nblocks)
{
    extern __shared__ char smem[];
    const uint32_t sb = smem_u32(smem);
    int*    gxS  = (int*)   (smem + OFF_GX);
    float*  bS   = (float*) (smem + OFF_BIA);
    float*  gS   = (float*) (smem + OFF_GAM);
    float*  btS  = (float*) (smem + OFF_BET);
    float*  psum = (float*) (smem + OFF_PSUM);
    float*  psq  = (float*) (smem + OFF_PSQ);
    int* qbuf[2] = { (int*)(smem + OFF_QS0), (int*)(smem + OFF_QS1) };

    const int tid  = threadIdx.x;
    const int wid  = tid >> 5;
    const int lane = tid & 31;

    // ---- One-time: split W into fp16 hi/lo padded tiles (22-bit coverage) ----
    for (int i = tid; i < DD * KK; i += NTHR) {
        int n = i >> 7, k = i & 127;
        float w = W[i];
        __half hi = __float2half_rn(w);
        __half lo = __float2half_rn(w - __half2float(hi));
        uint32_t off = (uint32_t)n * PADB + ((uint32_t)k << 1);
        *(__half*)(smem + OFF_BHI + off) = hi;
        *(__half*)(smem + OFF_BLO + off) = lo;
    }
    if (tid < NTOKN * GG) gxS[tid] = gidx[tid];
    if (tid < DD) { bS[tid] = bias[tid]; gS[tid] = gamma[tid]; btS[tid] = beta[tid]; }
    // is64 detection: int64 ids < 1000 -> odd 32-bit words all zero
    if (tid < 32) {
        const unsigned int* p = (const unsigned int*)ids_raw;
        int ok = (p[1 + 2*tid] == 0u) & (p[65 + 2*tid] == 0u) &
                 (p[129 + 2*tid] == 0u) & (p[193 + 2*tid] == 0u);
        ok = __all_sync(0xffffffffu, ok);
        if (tid == 0) *(int*)(smem + OFF_FLAG) = ok;
    }
    __syncthreads();
    const int is64 = *(int*)(smem + OFF_FLAG);

    // ---- gather constants: warp owns (tt, mb); lane = (token-parity, e-quad) ----
    const int tt  = wid & 1;              // table half (k = tt*64 + eq*4 + {0..3})
    const int mb  = wid >> 1;             // rows m ≡ mb (mod 8)
    const int t01 = lane >> 4;            // token parity: row = mb + s*16 + t01*8
    const int eq  = lane & 15;            // e-quad
    const int ntok = mb + t01 * 8;        // this lane's token (fixed!)
    int fL[GG];
    #pragma unroll
    for (int g = 0; g < GG; ++g) fL[g] = gxS[ntok * GG + g];
    const float* gbase = tbl + (size_t)tt * 4096000 + (eq << 2);
    // missing-emb vectors are group-invariant per lane: load ONCE
    float4 wmiss[GG];
    #pragma unroll
    for (int g = 0; g < GG; ++g)
        wmiss[g] = __ldg((const float4*)(missing + tt * 4096 + (fL[g] << 6) + (eq << 2)));
    char* aptr0 = smem + OFF_A0 + tt * 128 + eq * 8;    // + buf*ASZ + m*PADB

    // ---- GEMM warp mapping: 32m x 64n tiles (4m x 4n warp grid) ----
    const int mq = wid & 3;
    const int nq = wid >> 2;
    const uint32_t paH0 = sb + OFF_A0 + (uint32_t)(mq * 32 + (lane & 15)) * PADB
                        + (uint32_t)(lane >> 4) * 16;
    const int g8 = lane >> 3;
    const uint32_t pb = sb + ((g8 < 2) ? OFF_BHI : OFF_BLO)
                      + (uint32_t)(nq * 64 + (lane & 7)) * PADB
                      + (uint32_t)(g8 & 1) * 16;
    const int cbase = nq * 64 + (lane & 3) * 2;

    // ---- helpers ----
    auto stage_q = [&](int g, int* buf) {
        int gi  = g * (SBK * FF) + tid;
        int idv = is64 ? (int)__ldg((const long long*)ids_raw + gi)
                       : __ldg((const int*)ids_raw + gi);
        int f   = tid & 63;
        buf[tid] = (((f * VV + idv) << 6) << 1) | __ldg(mask + gi);
    };
    // standalone gather (prologue only)
    auto gather_all = [&](const int* buf, char* adst) {
        #pragma unroll 4
        for (int s = 0; s < 8; ++s) {
            const int* q = buf + (s << 6);
            int qm[GG];
            #pragma unroll
            for (int g = 0; g < GG; ++g) qm[g] = q[fL[g]];
            float4 v[GG];
            #pragma unroll
            for (int g = 0; g < GG; ++g)
                v[g] = __ldg((const float4*)(gbase + (qm[g] >> 1)));
            float x0 = 0.f, x1 = 0.f, x2 = 0.f, x3 = 0.f;
            #pragma unroll
            for (int g = 0; g < GG; ++g) {
                float mk = (float)(qm[g] & 1);
                x0 += v[g].x + mk * wmiss[g].x;
                x1 += v[g].y + mk * wmiss[g].y;
                x2 += v[g].z + mk * wmiss[g].z;
                x3 += v[g].w + mk * wmiss[g].w;
            }
            __half2 hp0 = __floats2half2_rn(x0 * 0.25f, x1 * 0.25f);
            __half2 hp1 = __floats2half2_rn(x2 * 0.25f, x3 * 0.25f);
            int m = mb + (s << 4) + (t01 << 3);
            *(uint2*)(adst + (uint32_t)m * PADB) =
                make_uint2(*(uint32_t*)&hp0, *(uint32_t*)&hp1);
        }
    };

    // ---- pipelined prologue ----
    int grp = blockIdx.x;
    stage_q(grp, qbuf[0]);
    __syncthreads();
    gather_all(qbuf[0], aptr0);               // A buffer 0 <- grp
    int nxt = grp + nblocks;
    if (nxt < NGRP) stage_q(nxt, qbuf[1]);
    __syncthreads();
    int abuf = 0, qsel = 1;

    while (true) {
        const bool dog = (nxt < NGRP);
        const int* qb = qbuf[qsel];
        char* adst = aptr0 + (abuf ^ 1) * ASZ;      // gather target (next group)
        const uint32_t pa = paH0 + (uint32_t)abuf * ASZ;

        // ---- fused: GEMM(grp) with gather(nxt) software-pipelined in ----
        float acc[2][8][4];
        #pragma unroll
        for (int t = 0; t < 2; ++t)
            #pragma unroll
            for (int j = 0; j < 8; ++j)
                #pragma unroll
                for (int c = 0; c < 4; ++c) acc[t][j][c] = 0.f;

        int    qm[GG];
        float4 v[GG];
        if (dog) {                                   // prefetch gather step 0
            #pragma unroll
            for (int g = 0; g < GG; ++g) qm[g] = qb[fL[g]];
            #pragma unroll
            for (int g = 0; g < GG; ++g)
                v[g] = __ldg((const float4*)(gbase + (qm[g] >> 1)));
        }

        #pragma unroll 1
        for (int s = 0; s < 8; ++s) {
            uint32_t aH0[4], aH1[4];
            ldm4(aH0, pa + s * 32);
            ldm4(aH1, pa + 16 * PADB + s * 32);
            uint32_t bc[4], bn[4];
            ldm4(bc, pb + s * 32);
            #pragma unroll
            for (int j = 0; j < 8; ++j) {
                if (j < 7) ldm4(bn, pb + (uint32_t)(j + 1) * (8 * PADB) + s * 32);
                mma16816(acc[0][j], aH0, bc[0], bc[1]);   // A * W_hi
                mma16816(acc[0][j], aH0, bc[2], bc[3]);   // A * W_lo
                mma16816(acc[1][j], aH1, bc[0], bc[1]);
                mma16816(acc[1][j], aH1, bc[2], bc[3]);
                #pragma unroll
                for (int z = 0; z < 4; ++z) bc[z] = bn[z];
            }
            if (dog) {
                // consume gather step s (loads issued one GEMM step ago)
                float x0 = 0.f, x1 = 0.f, x2 = 0.f, x3 = 0.f;
                #pragma unroll
                for (int g = 0; g < GG; ++g) {
                    float mk = (float)(qm[g] & 1);
                    x0 += v[g].x + mk * wmiss[g].x;
                    x1 += v[g].y + mk * wmiss[g].y;
                    x2 += v[g].z + mk * wmiss[g].z;
                    x3 += v[g].w + mk * wmiss[g].w;
                }
                __half2 hp0 = __floats2half2_rn(x0 * 0.25f, x1 * 0.25f);
                __half2 hp1 = __floats2half2_rn(x2 * 0.25f, x3 * 0.25f);
                int m = mb + (s << 4) + (t01 << 3);
                *(uint2*)(adst + (uint32_t)m * PADB) =
                    make_uint2(*(uint32_t*)&hp0, *(uint32_t*)&hp1);
                if (s < 7) {                         // prefetch gather step s+1
                    const int* q = qb + ((s + 1) << 6);
                    #pragma unroll
                    for (int g = 0; g < GG; ++g) qm[g] = q[fL[g]];
                    #pragma unroll
                    for (int g = 0; g < GG; ++g)
                        v[g] = __ldg((const float4*)(gbase + (qm[g] >> 1)));
                }
            }
        }

        // ---- bias + SiLU in regs; quad-reduce row partial sums ----
        float s_[2][2] = {{0.f,0.f},{0.f,0.f}}, q_[2][2] = {{0.f,0.f},{0.f,0.f}};
        #pragma unroll
        for (int t = 0; t < 2; ++t)
            #pragma unroll
            for (int j = 0; j < 8; ++j) {
                int c = cbase + j * 8;
                float2 bb = *(float2*)(bS + c);
                float v0 = silu(acc[t][j][0] + bb.x);
                float v1 = silu(acc[t][j][1] + bb.y);
                float v2 = silu(acc[t][j][2] + bb.x);
                float v3 = silu(acc[t][j][3] + bb.y);
                acc[t][j][0] = v0; acc[t][j][1] = v1;
                acc[t][j][2] = v2; acc[t][j][3] = v3;
                s_[t][0] += v0 + v1; q_[t][0] += v0*v0 + v1*v1;
                s_[t][1] += v2 + v3; q_[t][1] += v2*v2 + v3*v3;
            }
        #pragma unroll
        for (int o = 1; o <= 2; o <<= 1) {
            #pragma unroll
            for (int t = 0; t < 2; ++t)
                #pragma unroll
                for (int r = 0; r < 2; ++r) {
                    s_[t][r] += __shfl_xor_sync(0xffffffffu, s_[t][r], o);
                    q_[t][r] += __shfl_xor_sync(0xffffffffu, q_[t][r], o);
                }
        }
        if ((lane & 3) == 0) {
            #pragma unroll
            for (int t = 0; t < 2; ++t) {
                int r = mq * 32 + t * 16 + (lane >> 2);
                psum[r * 4 + nq] = s_[t][0];  psq[r * 4 + nq] = q_[t][0];
                psum[(r + 8) * 4 + nq] = s_[t][1];  psq[(r + 8) * 4 + nq] = q_[t][1];
            }
        }
        __syncthreads();   // psum ready; gather(nxt) -> A[abuf^1] complete

        // ---- stage q(nxt2); its LDG latency hides under the LN below ----
        int nxt2 = nxt + nblocks;
        if (dog && nxt2 < NGRP) stage_q(nxt2, qbuf[qsel ^ 1]);

        // ---- LN params from partials (LDS.128) + direct streaming stores ----
        #pragma unroll
        for (int t = 0; t < 2; ++t)
            #pragma unroll
            for (int rr = 0; rr < 2; ++rr) {
                int r = mq * 32 + t * 16 + (lane >> 2) + rr * 8;
                float4 ps = *(float4*)(psum + r * 4);
                float4 pq = *(float4*)(psq + r * 4);
                float mu  = (ps.x + ps.y + ps.z + ps.w) * (1.f / 256.f);
                float var = (pq.x + pq.y + pq.z + pq.w) * (1.f / 256.f) - mu * mu;
                float inv = rsqrtf(var + 1e-5f);
                float* dst = out + ((size_t)grp * MT + r) * DD;
                #pragma unroll
                for (int j = 0; j < 8; ++j) {
                    int c = cbase + j * 8;
                    float2 gg = *(float2*)(gS  + c);
                    float2 be = *(float2*)(btS + c);
                    stg_cs2(dst + c,
                            (acc[t][j][rr*2+0] - mu) * inv * gg.x + be.x,
                            (acc[t][j][rr*2+1] - mu) * inv * gg.y + be.y);
                }
            }

        __syncthreads();   // psum/qbuf safe to reuse
        if (!dog) break;
        grp = nxt; nxt = nxt2; abuf ^= 1; qsel ^= 1;
    }
}

extern "C" void kernel_launch(void* const* d_in, const int* in_sizes, int n_in,
                              void* d_out, int out_size) {
    const void*  ids     = d_in[0];
    const int*   mask    = (const int*)  d_in[1];
    const int*   gidx    = (const int*)  d_in[2];
    const float* tbl     = (const float*)d_in[3];
    const float* missing = (const float*)d_in[4];
    const float* W       = (const float*)d_in[5];
    const float* b       = (const float*)d_in[6];
    const float* gamma   = (const float*)d_in[7];
    const float* beta    = (const float*)d_in[8];
    float* out = (float*)d_out;

    int nsm = 0;
    cudaDeviceGetAttribute(&nsm, cudaDevAttrMultiProcessorCount, 0);
    if (nsm <= 0) nsm = 148;
    if (nsm > NGRP) nsm = NGRP;

    cudaFuncSetAttribute(fused_tokenizer_kernel,
                         cudaFuncAttributeMaxDynamicSharedMemorySize, SMEM_BYTES);

    fused_tokenizer_kernel<<<nsm, NTHR, SMEM_BYTES>>>(
        ids, mask, gidx, tbl, missing, W, b, gamma, beta, out, nsm);
}

// round 13
// speedup vs baseline: 4.4447x; 1.1199x over previous
#include <cuda_runtime.h>
#include <cuda_fp16.h>
#include <cstdint>

#define BB    8192
#define FF    64
#define VV    1000
#define NTOKN 16
#define GG    4
#define DD    256
#define KK    128
#define SBK   8
#define MT    128          // rows per group = SBK*NTOKN
#define NGRP  (BB / SBK)
#define NTHR  512

#define PADB  272          // bytes per fp16 tile row (136 halves): conflict-free ldmatrix
#define ASZ   34816        // one A tile (128 * PADB)

// smem byte offsets
#define OFF_BH   0                         // W fp16 [256][136]      69632 B
#define OFF_A0   69632                     // x fp16 tile, buffer 0  34816 B
#define OFF_A1   104448                    // x fp16 tile, buffer 1  34816 B
#define OFF_QS0  139264                    // 512 ints (double-buffered q)
#define OFF_QS1  141312
#define OFF_GX   143360                    // 64 ints
#define OFF_BIA  143616                    // 256 floats
#define OFF_GAM  144640
#define OFF_BET  145664
#define OFF_PSUM 146688                    // [128][4] floats
#define OFF_PSQ  148736                    // [128][4] floats
#define OFF_FLAG 150784                    // is64 flag
#define SMEM_BYTES 150816

__device__ __forceinline__ uint32_t smem_u32(const void* p) {
    uint32_t a;
    asm("{ .reg .u64 t; cvta.to.shared.u64 t, %1; cvt.u32.u64 %0, t; }" : "=r"(a) : "l"(p));
    return a;
}
__device__ __forceinline__ void ldm4(uint32_t* r, uint32_t addr) {
    asm volatile("ldmatrix.sync.aligned.m8n8.x4.shared.b16 {%0,%1,%2,%3}, [%4];"
                 : "=r"(r[0]), "=r"(r[1]), "=r"(r[2]), "=r"(r[3]) : "r"(addr));
}
__device__ __forceinline__ void mma16816(float* c, const uint32_t* a,
                                         uint32_t b0, uint32_t b1) {
    asm volatile("mma.sync.aligned.m16n8k16.row.col.f32.f16.f16.f32 "
                 "{%0,%1,%2,%3}, {%4,%5,%6,%7}, {%8,%9}, {%0,%1,%2,%3};"
                 : "+f"(c[0]), "+f"(c[1]), "+f"(c[2]), "+f"(c[3])
                 : "r"(a[0]), "r"(a[1]), "r"(a[2]), "r"(a[3]), "r"(b0), "r"(b1));
}
__device__ __forceinline__ void stg_cs2(float* p, float x, float y) {
    asm volatile("st.global.cs.v2.f32 [%0], {%1,%2};" :: "l"(p), "f"(x), "f"(y) : "memory");
}
__device__ __forceinline__ float silu(float v) { return v / (1.f + __expf(-v)); }

__global__ __launch_bounds__(NTHR, 1)
void fused_tokenizer_kernel(const void*  __restrict__ ids_raw,
                            const int*   __restrict__ mask,
                            const int*   __restrict__ gidx,
                            const float* __restrict__ tbl,
                            const float* __restrict__ missing,
                            const float* __restrict__ W,
                            const float* __restrict__ bias,
                            const float* __restrict__ gamma,
                            const float* __restrict__ beta,
                            float*       __restrict__ out,
                            int nblocks)
{
    extern __shared__ char smem[];
    const uint32_t sb = smem_u32(smem);
    int*    gxS  = (int*)   (smem + OFF_GX);
    float*  bS   = (float*) (smem + OFF_BIA);
    float*  gS   = (float*) (smem + OFF_GAM);
    float*  btS  = (float*) (smem + OFF_BET);
    float*  psum = (float*) (smem + OFF_PSUM);
    float*  psq  = (float*) (smem + OFF_PSQ);
    int* qbuf[2] = { (int*)(smem + OFF_QS0), (int*)(smem + OFF_QS1) };

    const int tid  = threadIdx.x;
    const int wid  = tid >> 5;
    const int lane = tid & 31;

    // ---- One-time: W -> fp16 padded tile ----
    for (int i = tid; i < DD * KK; i += NTHR) {
        int n = i >> 7, k = i & 127;
        uint32_t off = (uint32_t)n * PADB + ((uint32_t)k << 1);
        *(__half*)(smem + OFF_BH + off) = __float2half_rn(W[i]);
    }
    if (tid < NTOKN * GG) gxS[tid] = gidx[tid];
    if (tid < DD) { bS[tid] = bias[tid]; gS[tid] = gamma[tid]; btS[tid] = beta[tid]; }
    // is64 detection: int64 ids < 1000 -> odd 32-bit words all zero
    if (tid < 32) {
        const unsigned int* p = (const unsigned int*)ids_raw;
        int ok = (p[1 + 2*tid] == 0u) & (p[65 + 2*tid] == 0u) &
                 (p[129 + 2*tid] == 0u) & (p[193 + 2*tid] == 0u);
        ok = __all_sync(0xffffffffu, ok);
        if (tid == 0) *(int*)(smem + OFF_FLAG) = ok;
    }
    __syncthreads();
    const int is64 = *(int*)(smem + OFF_FLAG);

    // ---- gather constants: warp owns (tt, mb); lane = (token-parity, e-quad) ----
    const int tt  = wid & 1;              // table half (k = tt*64 + eq*4 + {0..3})
    const int mb  = wid >> 1;             // rows m ≡ mb (mod 8)
    const int t01 = lane >> 4;            // token parity: row = mb + s*16 + t01*8
    const int eq  = lane & 15;            // e-quad
    const int ntok = mb + t01 * 8;        // this lane's token (fixed!)
    int fL[GG];
    #pragma unroll
    for (int g = 0; g < GG; ++g) fL[g] = gxS[ntok * GG + g];
    const float* gbase = tbl + (size_t)tt * 4096000 + (eq << 2);
    // missing-emb vectors are group-invariant per lane: load ONCE
    float4 wmiss[GG];
    #pragma unroll
    for (int g = 0; g < GG; ++g)
        wmiss[g] = __ldg((const float4*)(missing + tt * 4096 + (fL[g] << 6) + (eq << 2)));
    char* aptr0 = smem + OFF_A0 + tt * 128 + eq * 8;    // + buf*ASZ + m*PADB

    // ---- GEMM warp mapping: 32m x 64n tiles (4m x 4n warp grid) ----
    const int mq = wid & 3;
    const int nq = wid >> 2;
    const uint32_t paH0 = sb + OFF_A0 + (uint32_t)(mq * 32 + (lane & 15)) * PADB
                        + (uint32_t)(lane >> 4) * 16;
    // B ldm4: frags {f0,f1} = n-rows [base,base+8) k s16/{lo,hi}; {f2,f3} = rows +8
    const uint32_t pb = sb + OFF_BH
                      + (uint32_t)(nq * 64 + (lane & 7) + ((lane >> 4) << 3)) * PADB
                      + (uint32_t)((lane >> 3) & 1) * 16;
    const int cbase = nq * 64 + (lane & 3) * 2;

    // ---- helpers ----
    auto stage_q = [&](int g, int* buf) {
        int gi  = g * (SBK * FF) + tid;
        int idv = is64 ? (int)__ldg((const long long*)ids_raw + gi)
                       : __ldg((const int*)ids_raw + gi);
        int f   = tid & 63;
        buf[tid] = (((f * VV + idv) << 6) << 1) | __ldg(mask + gi);
    };
    // standalone gather (prologue only)
    auto gather_all = [&](const int* buf, char* adst) {
        #pragma unroll 4
        for (int s = 0; s < 8; ++s) {
            const int* q = buf + (s << 6);
            int qm[GG];
            #pragma unroll
            for (int g = 0; g < GG; ++g) qm[g] = q[fL[g]];
            float4 v[GG];
            #pragma unroll
            for (int g = 0; g < GG; ++g)
                v[g] = __ldg((const float4*)(gbase + (qm[g] >> 1)));
            float x0 = 0.f, x1 = 0.f, x2 = 0.f, x3 = 0.f;
            #pragma unroll
            for (int g = 0; g < GG; ++g) {
                float mk = (float)(qm[g] & 1);
                x0 += v[g].x + mk * wmiss[g].x;
                x1 += v[g].y + mk * wmiss[g].y;
                x2 += v[g].z + mk * wmiss[g].z;
                x3 += v[g].w + mk * wmiss[g].w;
            }
            __half2 hp0 = __floats2half2_rn(x0 * 0.25f, x1 * 0.25f);
            __half2 hp1 = __floats2half2_rn(x2 * 0.25f, x3 * 0.25f);
            int m = mb + (s << 4) + (t01 << 3);
            *(uint2*)(adst + (uint32_t)m * PADB) =
                make_uint2(*(uint32_t*)&hp0, *(uint32_t*)&hp1);
        }
    };

    // ---- pipelined prologue ----
    int grp = blockIdx.x;
    stage_q(grp, qbuf[0]);
    __syncthreads();
    gather_all(qbuf[0], aptr0);               // A buffer 0 <- grp
    int nxt = grp + nblocks;
    if (nxt < NGRP) stage_q(nxt, qbuf[1]);
    __syncthreads();
    int abuf = 0, qsel = 1;

    while (true) {
        const bool dog = (nxt < NGRP);
        const int* qb = qbuf[qsel];
        char* adst = aptr0 + (abuf ^ 1) * ASZ;      // gather target (next group)
        const uint32_t pa = paH0 + (uint32_t)abuf * ASZ;

        // ---- fused: GEMM(grp) with gather(nxt) software-pipelined in ----
        float acc[2][8][4];
        #pragma unroll
        for (int t = 0; t < 2; ++t)
            #pragma unroll
            for (int j = 0; j < 8; ++j)
                #pragma unroll
                for (int c = 0; c < 4; ++c) acc[t][j][c] = 0.f;

        int    qm[GG];
        float4 v[GG];
        if (dog) {                                   // prefetch gather step 0
            #pragma unroll
            for (int g = 0; g < GG; ++g) qm[g] = qb[fL[g]];
            #pragma unroll
            for (int g = 0; g < GG; ++g)
                v[g] = __ldg((const float4*)(gbase + (qm[g] >> 1)));
        }

        #pragma unroll 1
        for (int s = 0; s < 8; ++s) {
            uint32_t aH0[4], aH1[4];
            ldm4(aH0, pa + s * 32);
            ldm4(aH1, pa + 16 * PADB + s * 32);
            uint32_t bc[4], bn[4];
            ldm4(bc, pb + s * 32);                   // n-frags 0,1
            #pragma unroll
            for (int jj = 0; jj < 4; ++jj) {         // 2 n-frags per ldm4
                if (jj < 3) ldm4(bn, pb + (uint32_t)(jj + 1) * (16 * PADB) + s * 32);
                mma16816(acc[0][jj*2],   aH0, bc[0], bc[1]);
                mma16816(acc[0][jj*2+1], aH0, bc[2], bc[3]);
                mma16816(acc[1][jj*2],   aH1, bc[0], bc[1]);
                mma16816(acc[1][jj*2+1], aH1, bc[2], bc[3]);
                #pragma unroll
                for (int z = 0; z < 4; ++z) bc[z] = bn[z];
            }
            if (dog) {
                // consume gather step s (loads issued one GEMM step ago)
                float x0 = 0.f, x1 = 0.f, x2 = 0.f, x3 = 0.f;
                #pragma unroll
                for (int g = 0; g < GG; ++g) {
                    float mk = (float)(qm[g] & 1);
                    x0 += v[g].x + mk * wmiss[g].x;
                    x1 += v[g].y + mk * wmiss[g].y;
                    x2 += v[g].z + mk * wmiss[g].z;
                    x3 += v[g].w + mk * wmiss[g].w;
                }
                __half2 hp0 = __floats2half2_rn(x0 * 0.25f, x1 * 0.25f);
                __half2 hp1 = __floats2half2_rn(x2 * 0.25f, x3 * 0.25f);
                int m = mb + (s << 4) + (t01 << 3);
                *(uint2*)(adst + (uint32_t)m * PADB) =
                    make_uint2(*(uint32_t*)&hp0, *(uint32_t*)&hp1);
                if (s < 7) {                         // prefetch gather step s+1
                    const int* q = qb + ((s + 1) << 6);
                    #pragma unroll
                    for (int g = 0; g < GG; ++g) qm[g] = q[fL[g]];
                    #pragma unroll
                    for (int g = 0; g < GG; ++g)
                        v[g] = __ldg((const float4*)(gbase + (qm[g] >> 1)));
                }
            }
        }

        // ---- bias + SiLU in regs; quad-reduce row partial sums ----
        float s_[2][2] = {{0.f,0.f},{0.f,0.f}}, q_[2][2] = {{0.f,0.f},{0.f,0.f}};
        #pragma unroll
        for (int t = 0; t < 2; ++t)
            #pragma unroll
            for (int j = 0; j < 8; ++j) {
                int c = cbase + j * 8;
                float2 bb = *(float2*)(bS + c);
                float v0 = silu(acc[t][j][0] + bb.x);
                float v1 = silu(acc[t][j][1] + bb.y);
                float v2 = silu(acc[t][j][2] + bb.x);
                float v3 = silu(acc[t][j][3] + bb.y);
                acc[t][j][0] = v0; acc[t][j][1] = v1;
                acc[t][j][2] = v2; acc[t][j][3] = v3;
                s_[t][0] += v0 + v1; q_[t][0] += v0*v0 + v1*v1;
                s_[t][1] += v2 + v3; q_[t][1] += v2*v2 + v3*v3;
            }
        #pragma unroll
        for (int o = 1; o <= 2; o <<= 1) {
            #pragma unroll
            for (int t = 0; t < 2; ++t)
                #pragma unroll
                for (int r = 0; r < 2; ++r) {
                    s_[t][r] += __shfl_xor_sync(0xffffffffu, s_[t][r], o);
                    q_[t][r] += __shfl_xor_sync(0xffffffffu, q_[t][r], o);
                }
        }
        if ((lane & 3) == 0) {
            #pragma unroll
            for (int t = 0; t < 2; ++t) {
                int r = mq * 32 + t * 16 + (lane >> 2);
                psum[r * 4 + nq] = s_[t][0];  psq[r * 4 + nq] = q_[t][0];
                psum[(r + 8) * 4 + nq] = s_[t][1];  psq[(r + 8) * 4 + nq] = q_[t][1];
            }
        }
        __syncthreads();   // psum ready; gather(nxt) -> A[abuf^1] complete

        // ---- stage q(nxt2); its LDG latency hides under the LN below ----
        int nxt2 = nxt + nblocks;
        if (dog && nxt2 < NGRP) stage_q(nxt2, qbuf[qsel ^ 1]);

        // ---- LN params from partials (LDS.128) + direct streaming stores ----
        #pragma unroll
        for (int t = 0; t < 2; ++t)
            #pragma unroll
            for (int rr = 0; rr < 2; ++rr) {
                int r = mq * 32 + t * 16 + (lane >> 2) + rr * 8;
                float4 ps = *(float4*)(psum + r * 4);
                float4 pq = *(float4*)(psq + r * 4);
                float mu  = (ps.x + ps.y + ps.z + ps.w) * (1.f / 256.f);
                float var = (pq.x + pq.y + pq.z + pq.w) * (1.f / 256.f) - mu * mu;
                float inv = rsqrtf(var + 1e-5f);
                float* dst = out + ((size_t)grp * MT + r) * DD;
                #pragma unroll
                for (int j = 0; j < 8; ++j) {
                    int c = cbase + j * 8;
                    float2 gg = *(float2*)(gS  + c);
                    float2 be = *(float2*)(btS + c);
                    stg_cs2(dst + c,
                            (acc[t][j][rr*2+0] - mu) * inv * gg.x + be.x,
                            (acc[t][j][rr*2+1] - mu) * inv * gg.y + be.y);
                }
            }

        __syncthreads();   // psum/qbuf safe to reuse
        if (!dog) break;
        grp = nxt; nxt = nxt2; abuf ^= 1; qsel ^= 1;
    }
}

extern "C" void kernel_launch(void* const* d_in, const int* in_sizes, int n_in,
                              void* d_out, int out_size) {
    const void*  ids     = d_in[0];
    const int*   mask    = (const int*)  d_in[1];
    const int*   gidx    = (const int*)  d_in[2];
    const float* tbl     = (const float*)d_in[3];
    const float* missing = (const float*)d_in[4];
    const float* W       = (const float*)d_in[5];
    const float* b       = (const float*)d_in[6];
    const float* gamma   = (const float*)d_in[7];
    const float* beta    = (const float*)d_in[8];
    float* out = (float*)d_out;

    int nsm = 0;
    cudaDeviceGetAttribute(&nsm, cudaDevAttrMultiProcessorCount, 0);
    if (nsm <= 0) nsm = 148;
    if (nsm > NGRP) nsm = NGRP;

    cudaFuncSetAttribute(fused_tokenizer_kernel,
                         cudaFuncAttributeMaxDynamicSharedMemorySize, SMEM_BYTES);

    fused_tokenizer_kernel<<<nsm, NTHR, SMEM_BYTES>>>(
        ids, mask, gidx, tbl, missing, W, b, gamma, beta, out, nsm);
}

// round 14
// speedup vs baseline: 5.3939x; 1.2135x over previous
#include <cuda_runtime.h>
#include <cuda_fp16.h>
#include <cstdint>

#define BB    8192
#define FF    64
#define VV    1000
#define NTOKN 16
#define GG    4
#define DD    256
#define KK    128
#define SBK   4
#define MT    64           // rows per group = SBK*NTOKN
#define NGRP  (BB / SBK)   // 2048
#define NTHR  512

#define PADB  272          // bytes per fp16 tile row (136 halves): conflict-free ldmatrix

// smem byte offsets  (total ~92KB -> 2 CTAs per SM)
#define OFF_BH   0                         // W fp16 [256][136]   69632 B
#define OFF_A    69632                     // x fp16 [64][136]    17408 B
#define OFF_QS0  87040                     // 256 ints
#define OFF_QS1  88064
#define OFF_GX   89088                     // 64 ints
#define OFF_BIA  89344                     // 256 floats
#define OFF_GAM  90368
#define OFF_BET  91392
#define OFF_PSUM 92416                     // [64][4] floats
#define OFF_PSQ  93440
#define OFF_FLAG 94464
#define SMEM_BYTES 94496

__device__ __forceinline__ uint32_t smem_u32(const void* p) {
    uint32_t a;
    asm("{ .reg .u64 t; cvta.to.shared.u64 t, %1; cvt.u32.u64 %0, t; }" : "=r"(a) : "l"(p));
    return a;
}
__device__ __forceinline__ void ldm4(uint32_t* r, uint32_t addr) {
    asm volatile("ldmatrix.sync.aligned.m8n8.x4.shared.b16 {%0,%1,%2,%3}, [%4];"
                 : "=r"(r[0]), "=r"(r[1]), "=r"(r[2]), "=r"(r[3]) : "r"(addr));
}
__device__ __forceinline__ void mma16816(float* c, const uint32_t* a,
                                         uint32_t b0, uint32_t b1) {
    asm volatile("mma.sync.aligned.m16n8k16.row.col.f32.f16.f16.f32 "
                 "{%0,%1,%2,%3}, {%4,%5,%6,%7}, {%8,%9}, {%0,%1,%2,%3};"
                 : "+f"(c[0]), "+f"(c[1]), "+f"(c[2]), "+f"(c[3])
                 : "r"(a[0]), "r"(a[1]), "r"(a[2]), "r"(a[3]), "r"(b0), "r"(b1));
}
__device__ __forceinline__ void stg_cs2(float* p, float x, float y) {
    asm volatile("st.global.cs.v2.f32 [%0], {%1,%2};" :: "l"(p), "f"(x), "f"(y) : "memory");
}
__device__ __forceinline__ float silu(float v) { return v / (1.f + __expf(-v)); }

__global__ __launch_bounds__(NTHR, 2)
void fused_tokenizer_kernel(const void*  __restrict__ ids_raw,
                            const int*   __restrict__ mask,
                            const int*   __restrict__ gidx,
                            const float* __restrict__ tbl,
                            const float* __restrict__ missing,
                            const float* __restrict__ W,
                            const float* __restrict__ bias,
                            const float* __restrict__ gamma,
                            const float* __restrict__ beta,
                            float*       __restrict__ out,
                            int nblocks)
{
    extern __shared__ char smem[];
    const uint32_t sb = smem_u32(smem);
    int*    gxS  = (int*)   (smem + OFF_GX);
    float*  bS   = (float*) (smem + OFF_BIA);
    float*  gS   = (float*) (smem + OFF_GAM);
    float*  btS  = (float*) (smem + OFF_BET);
    float*  psum = (float*) (smem + OFF_PSUM);
    float*  psq  = (float*) (smem + OFF_PSQ);
    int* qbuf[2] = { (int*)(smem + OFF_QS0), (int*)(smem + OFF_QS1) };

    const int tid  = threadIdx.x;
    const int wid  = tid >> 5;
    const int lane = tid & 31;

    // ---- One-time: W -> fp16 padded tile ----
    for (int i = tid; i < DD * KK; i += NTHR) {
        int n = i >> 7, k = i & 127;
        uint32_t off = (uint32_t)n * PADB + ((uint32_t)k << 1);
        *(__half*)(smem + OFF_BH + off) = __float2half_rn(W[i]);
    }
    if (tid < NTOKN * GG) gxS[tid] = gidx[tid];
    if (tid < DD) { bS[tid] = bias[tid]; gS[tid] = gamma[tid]; btS[tid] = beta[tid]; }
    // is64 detection: int64 ids < 1000 -> odd 32-bit words all zero
    if (tid < 32) {
        const unsigned int* p = (const unsigned int*)ids_raw;
        int ok = (p[1 + 2*tid] == 0u) & (p[65 + 2*tid] == 0u) &
                 (p[129 + 2*tid] == 0u) & (p[193 + 2*tid] == 0u);
        ok = __all_sync(0xffffffffu, ok);
        if (tid == 0) *(int*)(smem + OFF_FLAG) = ok;
    }
    __syncthreads();
    const int is64 = *(int*)(smem + OFF_FLAG);

    // ---- gather constants: warp owns (tt, mb); lane = (token-parity, e-quad) ----
    const int tt  = wid & 1;              // table half
    const int mb  = wid >> 1;             // 0..7
    const int t01 = lane >> 4;
    const int eq  = lane & 15;
    const int ntok = mb + t01 * 8;        // fixed token for this lane
    int fL[GG];
    #pragma unroll
    for (int g = 0; g < GG; ++g) fL[g] = gxS[ntok * GG + g];
    const float* gbase = tbl + (size_t)tt * 4096000 + (eq << 2);
    const float* mbase = missing + tt * 4096 + (eq << 2);
    char* aptr = smem + OFF_A + tt * 128 + eq * 8;      // + m*PADB per row

    // ---- GEMM warp mapping: 16m x 64n tiles (4m x 4n warp grid) ----
    const int mq = wid >> 2;
    const int nq = wid & 3;
    const uint32_t pa = sb + OFF_A + (uint32_t)(mq * 16 + (lane & 15)) * PADB
                      + (uint32_t)(lane >> 4) * 16;
    const uint32_t pb = sb + OFF_BH
                      + (uint32_t)(nq * 64 + (lane & 7) + ((lane >> 4) << 3)) * PADB
                      + (uint32_t)((lane >> 3) & 1) * 16;
    const int cbase = nq * 64 + (lane & 3) * 2;

    auto stage_q = [&](int g, int* buf) {
        if (tid < SBK * FF) {
            int gi  = g * (SBK * FF) + tid;
            int idv = is64 ? (int)__ldg((const long long*)ids_raw + gi)
                           : __ldg((const int*)ids_raw + gi);
            int f   = tid & 63;
            buf[tid] = (((f * VV + idv) << 6) << 1) | __ldg(mask + gi);
        }
    };
    auto gather = [&](const int* buf) {
        #pragma unroll
        for (int s = 0; s < SBK; ++s) {
            const int* q = buf + (s << 6);
            int qm[GG];
            #pragma unroll
            for (int g = 0; g < GG; ++g) qm[g] = q[fL[g]];
            float4 v[GG], w[GG];
            #pragma unroll
            for (int g = 0; g < GG; ++g)
                v[g] = __ldg((const float4*)(gbase + (qm[g] >> 1)));
            #pragma unroll
            for (int g = 0; g < GG; ++g)
                w[g] = __ldg((const float4*)(mbase + (fL[g] << 6)));  // L1-resident
            float x0 = 0.f, x1 = 0.f, x2 = 0.f, x3 = 0.f;
            #pragma unroll
            for (int g = 0; g < GG; ++g) {
                float mk = (float)(qm[g] & 1);
                x0 += v[g].x + mk * w[g].x;
                x1 += v[g].y + mk * w[g].y;
                x2 += v[g].z + mk * w[g].z;
                x3 += v[g].w + mk * w[g].w;
            }
            __half2 hp0 = __floats2half2_rn(x0 * 0.25f, x1 * 0.25f);
            __half2 hp1 = __floats2half2_rn(x2 * 0.25f, x3 * 0.25f);
            int m = (s << 4) + ntok;
            *(uint2*)(aptr + (uint32_t)m * PADB) =
                make_uint2(*(uint32_t*)&hp0, *(uint32_t*)&hp1);
        }
    };

    // ---- prologue ----
    int grp = blockIdx.x;
    stage_q(grp, qbuf[0]);
    __syncthreads();
    int qsel = 0;

    while (grp < NGRP) {
        // ---- gather(grp) -> A; stage q(next) under its latency ----
        gather(qbuf[qsel]);
        int nxt = grp + nblocks;
        if (nxt < NGRP) stage_q(nxt, qbuf[qsel ^ 1]);
        __syncthreads();   // A ready; q(nxt) staged; prev LN psum-reads done

        // ---- GEMM: 64x256x128 fp16 HMMA ----
        float acc[8][4];
        #pragma unroll
        for (int j = 0; j < 8; ++j)
            #pragma unroll
            for (int c = 0; c < 4; ++c) acc[j][c] = 0.f;

        #pragma unroll 1
        for (int s = 0; s < 8; ++s) {
            uint32_t aH[4];
            ldm4(aH, pa + s * 32);
            uint32_t bc[4], bn[4];
            ldm4(bc, pb + s * 32);
            #pragma unroll
            for (int jj = 0; jj < 4; ++jj) {       // 2 n-frags per ldm4
                if (jj < 3) ldm4(bn, pb + (uint32_t)(jj + 1) * (16 * PADB) + s * 32);
                mma16816(acc[jj*2],   aH, bc[0], bc[1]);
                mma16816(acc[jj*2+1], aH, bc[2], bc[3]);
                #pragma unroll
                for (int z = 0; z < 4; ++z) bc[z] = bn[z];
            }
        }

        // ---- bias + SiLU in regs; quad-reduce row partial sums ----
        float s_[2] = {0.f, 0.f}, q_[2] = {0.f, 0.f};
        #pragma unroll
        for (int j = 0; j < 8; ++j) {
            int c = cbase + j * 8;
            float2 bb = *(float2*)(bS + c);
            float v0 = silu(acc[j][0] + bb.x);
            float v1 = silu(acc[j][1] + bb.y);
            float v2 = silu(acc[j][2] + bb.x);
            float v3 = silu(acc[j][3] + bb.y);
            acc[j][0] = v0; acc[j][1] = v1; acc[j][2] = v2; acc[j][3] = v3;
            s_[0] += v0 + v1; q_[0] += v0*v0 + v1*v1;
            s_[1] += v2 + v3; q_[1] += v2*v2 + v3*v3;
        }
        #pragma unroll
        for (int o = 1; o <= 2; o <<= 1) {
            #pragma unroll
            for (int r = 0; r < 2; ++r) {
                s_[r] += __shfl_xor_sync(0xffffffffu, s_[r], o);
                q_[r] += __shfl_xor_sync(0xffffffffu, q_[r], o);
            }
        }
        if ((lane & 3) == 0) {
            int r = mq * 16 + (lane >> 2);
            psum[r * 4 + nq] = s_[0];        psq[r * 4 + nq] = q_[0];
            psum[(r + 8) * 4 + nq] = s_[1];  psq[(r + 8) * 4 + nq] = q_[1];
        }
        __syncthreads();   // psum ready; A reads complete (next gather may overwrite)

        // ---- LN params from partials + direct streaming stores ----
        #pragma unroll
        for (int rr = 0; rr < 2; ++rr) {
            int r = mq * 16 + (lane >> 2) + rr * 8;
            float4 ps = *(float4*)(psum + r * 4);
            float4 pq = *(float4*)(psq + r * 4);
            float mu  = (ps.x + ps.y + ps.z + ps.w) * (1.f / 256.f);
            float var = (pq.x + pq.y + pq.z + pq.w) * (1.f / 256.f) - mu * mu;
            float inv = rsqrtf(var + 1e-5f);
            float* dst = out + ((size_t)grp * MT + r) * DD;
            #pragma unroll
            for (int j = 0; j < 8; ++j) {
                int c = cbase + j * 8;
                float2 gg = *(float2*)(gS  + c);
                float2 be = *(float2*)(btS + c);
                stg_cs2(dst + c,
                        (acc[j][rr*2+0] - mu) * inv * gg.x + be.x,
                        (acc[j][rr*2+1] - mu) * inv * gg.y + be.y);
            }
        }

        grp = nxt; qsel ^= 1;
    }
}

extern "C" void kernel_launch(void* const* d_in, const int* in_sizes, int n_in,
                              void* d_out, int out_size) {
    const void*  ids     = d_in[0];
    const int*   mask    = (const int*)  d_in[1];
    const int*   gidx    = (const int*)  d_in[2];
    const float* tbl     = (const float*)d_in[3];
    const float* missing = (const float*)d_in[4];
    const float* W       = (const float*)d_in[5];
    const float* b       = (const float*)d_in[6];
    const float* gamma   = (const float*)d_in[7];
    const float* beta    = (const float*)d_in[8];
    float* out = (float*)d_out;

    int nsm = 0;
    cudaDeviceGetAttribute(&nsm, cudaDevAttrMultiProcessorCount, 0);
    if (nsm <= 0) nsm = 148;
    int nblk = 2 * nsm;                 // 2 CTAs per SM
    if (nblk > NGRP) nblk = NGRP;

    cudaFuncSetAttribute(fused_tokenizer_kernel,
                         cudaFuncAttributeMaxDynamicSharedMemorySize, SMEM_BYTES);

    fused_tokenizer_kernel<<<nblk, NTHR, SMEM_BYTES>>>(
        ids, mask, gidx, tbl, missing, W, b, gamma, beta, out, nblk);
}